// round 6
// baseline (speedup 1.0000x reference)
#include <cuda_runtime.h>
#include <cuda_bf16.h>
#include <math.h>
#include <stdint.h>

typedef unsigned int u32;
typedef unsigned long long u64;

#define BMAX 65536

// ---------------------------------------------------------------------------
// Device scratch.
//  g_qkv : qkv bf16                  [3B, 768]
//  g_ctx : attention ctx bf16 single [3B, 256]
//  g_hh  : LN2(fused) split bf16     [B, 512]  (hi | lo)
//  g_h2  : GELU(h@w1) split bf16     [B, 512]
//  g_w   : split weights             [rows, 512]
// ---------------------------------------------------------------------------
__device__ __nv_bfloat16 g_qkv[(size_t)BMAX * 3 * 768];
__device__ __nv_bfloat16 g_ctx[(size_t)BMAX * 3 * 256];
__device__ __nv_bfloat16 g_hh [(size_t)BMAX * 512];
__device__ __nv_bfloat16 g_h2 [(size_t)BMAX * 512];
__device__ __nv_bfloat16 g_w  [(size_t)(768 + 256 + 256 + 128) * 512];

#define WOFF_QKV 0
#define WOFF_OUT (768 * 512)
#define WOFF_W1  ((768 + 256) * 512)
#define WOFF_W2  ((768 + 512) * 512)

__device__ __forceinline__ u32 smem_u32(const void* p) {
    u32 a;
    asm("{ .reg .u64 t; cvta.to.shared.u64 t, %1; cvt.u32.u64 %0, t; }" : "=r"(a) : "l"(p));
    return a;
}
__device__ __forceinline__ float geluf(float x) {
    return 0.5f * x * (1.0f + erff(x * 0.7071067811865476f));
}
__device__ __forceinline__ float wsum(float v) {
    #pragma unroll
    for (int o = 16; o > 0; o >>= 1) v += __shfl_xor_sync(0xffffffffu, v, o);
    return v;
}
__device__ __forceinline__ u32 bf2bits(__nv_bfloat162 h) {
    return *reinterpret_cast<u32*>(&h);
}
__device__ __forceinline__ void split2(float a, float b, u32& h, u32& l) {
    __nv_bfloat162 hh = __floats2bfloat162_rn(a, b);
    float ra = a - __bfloat162float(hh.x);
    float rb = b - __bfloat162float(hh.y);
    __nv_bfloat162 ll = __floats2bfloat162_rn(ra, rb);
    h = bf2bits(hh);
    l = bf2bits(ll);
}

// ---------------------------------------------------------------------------
// merged weight conversion: fp32 [rows,256] -> split bf16 [rows,512]
// rows: [0,768)=in_proj, [768,1024)=out_w, [1024,1280)=w1, [1280,1408)=w2
// ---------------------------------------------------------------------------
__global__ __launch_bounds__(256)
void conv_w_all(const float* __restrict__ ipw, const float* __restrict__ ow,
                const float* __restrict__ w1, const float* __restrict__ w2)
{
    int id = blockIdx.x * 256 + threadIdx.x;     // 1408*64 total
    int row = id >> 6;
    int k = (id & 63) << 2;
    const float* src; int r, woff;
    if (row < 768)       { src = ipw; r = row;        woff = WOFF_QKV; }
    else if (row < 1024) { src = ow;  r = row - 768;  woff = WOFF_OUT; }
    else if (row < 1280) { src = w1;  r = row - 1024; woff = WOFF_W1; }
    else                 { src = w2;  r = row - 1280; woff = WOFF_W2; }
    float4 v = *(const float4*)(src + (size_t)r * 256 + k);
    u32 h0, l0, h1, l1;
    split2(v.x, v.y, h0, l0);
    split2(v.z, v.w, h1, l1);
    __nv_bfloat16* dst = g_w + (size_t)woff + (size_t)row * 512;
    // note row here indexes the merged table; use r for local row
    dst = g_w + (size_t)woff + (size_t)r * 512;
    u32* hp = (u32*)(dst + k);
    u32* lp = (u32*)(dst + 256 + k);
    hp[0] = h0; hp[1] = h1;
    lp[0] = l0; lp[1] = l1;
}

// ---------------------------------------------------------------------------
// MMA helpers
// ---------------------------------------------------------------------------
__device__ __forceinline__ void ldsm4(u32 addr, u32& r0, u32& r1, u32& r2, u32& r3) {
    asm volatile("ldmatrix.sync.aligned.m8n8.x4.shared.b16 {%0,%1,%2,%3}, [%4];"
                 : "=r"(r0), "=r"(r1), "=r"(r2), "=r"(r3) : "r"(addr));
}
__device__ __forceinline__ void mma16816(float* c, const u32* a, u32 b0, u32 b1) {
    asm volatile(
        "mma.sync.aligned.m16n8k16.row.col.f32.bf16.bf16.f32 "
        "{%0,%1,%2,%3}, {%4,%5,%6,%7}, {%8,%9}, {%0,%1,%2,%3};"
        : "+f"(c[0]), "+f"(c[1]), "+f"(c[2]), "+f"(c[3])
        : "r"(a[0]), "r"(a[1]), "r"(a[2]), "r"(a[3]), "r"(b0), "r"(b1));
}

// load ROWS x 128B chunk into SW128-swizzled smem via cp.async
template<int ROWS, int ROWB>
__device__ __forceinline__ void load_tile(u32 sbase, const char* gb) {
    constexpr int ITERS = ROWS * 8 / 256;
    int tid = threadIdx.x;
    #pragma unroll
    for (int i = 0; i < ITERS; i++) {
        int seg = i * 256 + tid;
        int r = seg >> 3, c = seg & 7;
        u32 off = (u32)(r * 128 + c * 16);
        off ^= (off >> 3) & 0x70;
        asm volatile("cp.async.cg.shared.global [%0], [%1], 16;"
                     :: "r"(sbase + off), "l"(gb + (size_t)r * ROWB + c * 16));
    }
}

// MODE 0: A = fp32 features (direct convert), 128 rows; load chunk c (64 floats)
__device__ __forceinline__ void load_Afeat(u32 sbase, int m0, int c,
                                           const float* __restrict__ s0,
                                           const float* __restrict__ s1,
                                           const float* __restrict__ s2)
{
    int tid = threadIdx.x;
    #pragma unroll
    for (int i = 0; i < 4; i++) {
        int seg = i * 256 + tid;          // 1024 units of 16B bf16 (=8 floats)
        int r = seg >> 3, c8 = seg & 7;
        int m = m0 + r;
        int b = m / 3, t = m - 3 * b;
        const float* src = ((t == 0) ? s0 : (t == 1) ? s1 : s2)
                           + (size_t)b * 256 + c * 64 + c8 * 8;
        float4 v0 = *(const float4*)src;
        float4 v1 = *(const float4*)(src + 4);
        u32 w0 = bf2bits(__floats2bfloat162_rn(v0.x, v0.y));
        u32 w1 = bf2bits(__floats2bfloat162_rn(v0.z, v0.w));
        u32 w2 = bf2bits(__floats2bfloat162_rn(v1.x, v1.y));
        u32 w3 = bf2bits(__floats2bfloat162_rn(v1.z, v1.w));
        u32 off = (u32)(r * 128 + c8 * 16);
        off ^= (off >> 3) & 0x70;
        asm volatile("st.shared.v4.b32 [%0], {%1,%2,%3,%4};"
                     :: "r"(sbase + off), "r"(w0), "r"(w1), "r"(w2), "r"(w3));
    }
}

// ---------------------------------------------------------------------------
// gemm_mma: 128x128 tile GEMMs.
// MODE 0: A = features fp32->bf16 direct, W=in_proj split (NP=8) -> g_qkv bf16
// MODE 2: A = g_hh split (NP=12), W=w1 split, +bias GELU split   -> g_h2
// MODE 3: A = g_h2 split (NP=12), W=w2 split, +bias GELU -> smem -> logits
// ---------------------------------------------------------------------------
template<int MODE>
__global__ __launch_bounds__(256)
void gemm_mma(const float* __restrict__ bias,
              const float* __restrict__ p0, const float* __restrict__ p1,
              const float* __restrict__ p2,
              const float* __restrict__ w3p, const float* __restrict__ b3p,
              float* __restrict__ outp)
{
    constexpr int NP   = (MODE == 0) ? 8 : 12;
    constexpr int NCHA = (MODE == 0) ? 4 : 8;

    extern __shared__ char dsm[];
    char* dbase = (char*)((((uintptr_t)dsm) + 1023) & ~(uintptr_t)1023);
    u32 base = smem_u32(dbase);
    const u32 wbase = base + NCHA * 16384;

    __shared__ float s_w3[896];
    __shared__ float s_b3[8];
    if constexpr (MODE == 3) {
        for (int i = threadIdx.x; i < 896; i += 256) s_w3[i] = w3p[i];
        if (threadIdx.x < 7) s_b3[threadIdx.x] = b3p[threadIdx.x];
    }

    const int tid = threadIdx.x;
    const int lane = tid & 31;
    const int wid = tid >> 5;
    const int warp_m = wid & 3;
    const int warp_n = wid >> 2;

    const int n0 = blockIdx.x * 128;
    const int m0 = blockIdx.y * 128;

    const __nv_bfloat16* Ap = nullptr;
    const __nv_bfloat16* Wp;
    if constexpr (MODE == 0)      {              Wp = g_w + WOFF_QKV; }
    else if constexpr (MODE == 2) { Ap = g_hh;   Wp = g_w + WOFF_W1; }
    else                          { Ap = g_h2;   Wp = g_w + WOFF_W2; }

    const char* Ab = (const char*)Ap + (size_t)m0 * 1024;
    const char* Wb = (const char*)Wp + (size_t)n0 * 1024;

    const int a_idx12[12] = {0,1,2,3, 0,1,2,3, 4,5,6,7};
    const int w_idx12[12] = {0,1,2,3, 4,5,6,7, 0,1,2,3};

    float acc[2][8][4];
    #pragma unroll
    for (int i = 0; i < 2; i++)
        #pragma unroll
        for (int j = 0; j < 8; j++)
            #pragma unroll
            for (int q = 0; q < 4; q++) acc[i][j][q] = 0.f;

    const int a_mi = lane >> 3;
    const int a_row_base = ((a_mi & 1) << 3) + (lane & 7);
    const int a_kb_sel = (lane >> 4) << 4;
    const int b_row_base = ((a_mi >> 1) << 3) + (lane & 7);
    const int b_kb_sel = ((lane >> 3) & 1) << 4;

    // W prologue first (async engine overlaps A conversion for MODE 0)
    load_tile<128, 1024>(wbase, Wb);
    if constexpr (MODE == 0) {
        asm volatile("cp.async.commit_group;");
        #pragma unroll
        for (int c = 0; c < 4; c++)
            load_Afeat(base + c * 16384, m0, c, p0, p1, p2);
    } else {
        #pragma unroll
        for (int c = 0; c < NCHA; c++)
            load_tile<128, 1024>(base + c * 16384, Ab + c * 128);
        asm volatile("cp.async.commit_group;");
    }

    #pragma unroll
    for (int kc = 0; kc < NP; kc++) {
        const int ai = (MODE == 0) ? (kc & 3) : a_idx12[kc];
        if (kc + 1 < NP) {
            const int wi = (MODE == 0) ? (kc + 1) : w_idx12[kc + 1];
            load_tile<128, 1024>(wbase + ((kc + 1) & 1) * 16384, Wb + wi * 128);
            asm volatile("cp.async.commit_group;");
            asm volatile("cp.async.wait_group 1;");
        } else {
            asm volatile("cp.async.wait_group 0;");
        }
        __syncthreads();

        const u32 As = base + ai * 16384;
        const u32 Bs = wbase + (kc & 1) * 16384;
        #pragma unroll
        for (int ks = 0; ks < 4; ks++) {
            u32 a[2][4];
            #pragma unroll
            for (int fm = 0; fm < 2; fm++) {
                int row = warp_m * 32 + fm * 16 + a_row_base;
                u32 kb = (u32)(ks * 32 + a_kb_sel);
                u32 ad = As + row * 128 + (kb ^ ((row & 7) << 4));
                ldsm4(ad, a[fm][0], a[fm][1], a[fm][2], a[fm][3]);
            }
            u32 b[4][4];
            #pragma unroll
            for (int fn = 0; fn < 4; fn++) {
                int row = warp_n * 64 + fn * 16 + b_row_base;
                u32 kb = (u32)(ks * 32 + b_kb_sel);
                u32 bd = Bs + row * 128 + (kb ^ ((row & 7) << 4));
                ldsm4(bd, b[fn][0], b[fn][1], b[fn][2], b[fn][3]);
            }
            #pragma unroll
            for (int fm = 0; fm < 2; fm++)
                #pragma unroll
                for (int f8 = 0; f8 < 8; f8++)
                    mma16816(acc[fm][f8], a[fm],
                             b[f8 >> 1][(f8 & 1) * 2], b[f8 >> 1][(f8 & 1) * 2 + 1]);
        }
        __syncthreads();
    }

    // ------------------------- epilogue -------------------------
    const int quad = lane >> 2, tq = lane & 3;
    float* h3_s = (float*)dbase;    // MODE 3: [128][128] fp32 (A region dead)

    #pragma unroll
    for (int fm = 0; fm < 2; fm++) {
        const int mA = m0 + warp_m * 32 + fm * 16 + quad;
        #pragma unroll
        for (int f8 = 0; f8 < 8; f8++) {
            const int n = n0 + warp_n * 64 + f8 * 8 + 2 * tq;
            float2 bv = *(const float2*)&bias[n];
            float v0 = acc[fm][f8][0] + bv.x;
            float v1 = acc[fm][f8][1] + bv.y;
            float v2 = acc[fm][f8][2] + bv.x;
            float v3 = acc[fm][f8][3] + bv.y;
            if constexpr (MODE == 0) {
                *(u32*)&g_qkv[(size_t)mA * 768 + n]       = bf2bits(__floats2bfloat162_rn(v0, v1));
                *(u32*)&g_qkv[(size_t)(mA + 8) * 768 + n] = bf2bits(__floats2bfloat162_rn(v2, v3));
            } else if constexpr (MODE == 2) {
                u32 h0, l0, h1, l1;
                split2(geluf(v0), geluf(v1), h0, l0);
                split2(geluf(v2), geluf(v3), h1, l1);
                *(u32*)&g_h2[(size_t)mA * 512 + n]             = h0;
                *(u32*)&g_h2[(size_t)mA * 512 + 256 + n]       = l0;
                *(u32*)&g_h2[(size_t)(mA + 8) * 512 + n]       = h1;
                *(u32*)&g_h2[(size_t)(mA + 8) * 512 + 256 + n] = l1;
            } else {
                int rl = warp_m * 32 + fm * 16 + quad;
                *(float2*)&h3_s[rl * 128 + n]       = {geluf(v0), geluf(v1)};
                *(float2*)&h3_s[(rl + 8) * 128 + n] = {geluf(v2), geluf(v3)};
            }
        }
    }

    if constexpr (MODE == 3) {
        __syncthreads();
        const int d0 = lane * 4;
        float4 wv[7];
        #pragma unroll
        for (int j = 0; j < 7; j++) wv[j] = *(const float4*)&s_w3[j * 128 + d0];
        #pragma unroll 1
        for (int rr = 0; rr < 16; rr++) {
            int row = wid * 16 + rr;
            float4 h = *(const float4*)&h3_s[row * 128 + d0];
            float r[7];
            #pragma unroll
            for (int j = 0; j < 7; j++) {
                float p = h.x * wv[j].x + h.y * wv[j].y + h.z * wv[j].z + h.w * wv[j].w;
                r[j] = wsum(p);
            }
            if (lane == 0) {
                #pragma unroll
                for (int j = 0; j < 7; j++)
                    outp[(size_t)(m0 + row) * 7 + j] = r[j] + s_b3[j];
            }
        }
    }
}

// ---------------------------------------------------------------------------
// attention: warp per token batch; reads bf16 qkv, writes ctx bf16 single
// ---------------------------------------------------------------------------
__global__ __launch_bounds__(256)
void attn_k(int B)
{
    int warp = threadIdx.x >> 5, lane = threadIdx.x & 31;
    int b = blockIdx.x * 8 + warp;
    if (b >= B) return;
    int d0 = lane * 8;

    float q[3][8], k[3][8], v[3][8];
    #pragma unroll
    for (int t = 0; t < 3; t++) {
        const __nv_bfloat16* row = g_qkv + ((size_t)b * 3 + t) * 768;
        uint4 qr = *(const uint4*)(row + d0);
        uint4 kr = *(const uint4*)(row + 256 + d0);
        uint4 vr = *(const uint4*)(row + 512 + d0);
        const u32* qw = (const u32*)&qr;
        const u32* kw = (const u32*)&kr;
        const u32* vw = (const u32*)&vr;
        #pragma unroll
        for (int j = 0; j < 4; j++) {
            float2 qf = __bfloat1622float2(*(const __nv_bfloat162*)&qw[j]);
            float2 kf = __bfloat1622float2(*(const __nv_bfloat162*)&kw[j]);
            float2 vf = __bfloat1622float2(*(const __nv_bfloat162*)&vw[j]);
            q[t][2*j] = qf.x; q[t][2*j+1] = qf.y;
            k[t][2*j] = kf.x; k[t][2*j+1] = kf.y;
            v[t][2*j] = vf.x; v[t][2*j+1] = vf.y;
        }
    }
    float s[3][3];
    #pragma unroll
    for (int t = 0; t < 3; t++)
        #pragma unroll
        for (int u = 0; u < 3; u++) {
            float p = 0.f;
            #pragma unroll
            for (int j = 0; j < 8; j++) p += q[t][j] * k[u][j];
            p += __shfl_xor_sync(0xffffffffu, p, 1);
            p += __shfl_xor_sync(0xffffffffu, p, 2);
            p += __shfl_xor_sync(0xffffffffu, p, 4);
            s[t][u] = p * 0.125f;
        }
    #pragma unroll
    for (int t = 0; t < 3; t++) {
        float mx = fmaxf(s[t][0], fmaxf(s[t][1], s[t][2]));
        float e0 = expf(s[t][0] - mx);
        float e1 = expf(s[t][1] - mx);
        float e2 = expf(s[t][2] - mx);
        float inv = 1.f / (e0 + e1 + e2);
        u32 cw[4];
        #pragma unroll
        for (int j = 0; j < 8; j += 2) {
            float c0 = (e0 * v[0][j]   + e1 * v[1][j]   + e2 * v[2][j])   * inv;
            float c1 = (e0 * v[0][j+1] + e1 * v[1][j+1] + e2 * v[2][j+1]) * inv;
            cw[j >> 1] = bf2bits(__floats2bfloat162_rn(c0, c1));
        }
        *(uint4*)(g_ctx + ((size_t)b * 3 + t) * 256 + d0) = *(uint4*)cw;
    }
}

// ---------------------------------------------------------------------------
// gemm_fuse: out-proj GEMM (M_TILE=96, N=256, ctx x out_w-hi, NP=4)
// fused with: +bias +residual, LN1, gate softmax, fused output, LN2, split.
// 8 warps as 2(m) x 4(n), warp tile 48x64 -> acc[3][8][4].
// ---------------------------------------------------------------------------
__global__ __launch_bounds__(256)
void gemm_fuse(const float* __restrict__ out_b,
               const float* __restrict__ s0, const float* __restrict__ s1,
               const float* __restrict__ s2,
               const float* __restrict__ ln1g, const float* __restrict__ ln1b,
               const float* __restrict__ gw,   const float* __restrict__ gbias,
               const float* __restrict__ ln2g, const float* __restrict__ ln2b,
               float* __restrict__ out_fused)
{
    extern __shared__ char dsm[];
    char* dbase = (char*)((((uintptr_t)dsm) + 1023) & ~(uintptr_t)1023);
    u32 base = smem_u32(dbase);
    const u32 wbase = base + 4 * 12288;          // A: 4 x 96x128B chunks

    __shared__ float s_gw[2304];
    __shared__ float s_ln[1024];
    __shared__ float s_bias[256];
    for (int i = threadIdx.x; i < 2304; i += 256) s_gw[i] = gw[i];
    {
        int i = threadIdx.x;
        s_ln[i]       = ln1g[i];
        s_ln[256 + i] = ln1b[i];
        s_ln[512 + i] = ln2g[i];
        s_ln[768 + i] = ln2b[i];
        s_bias[i]     = out_b[i];
    }

    const int tid = threadIdx.x;
    const int lane = tid & 31;
    const int wid = tid >> 5;
    const int warp_m = wid & 1;       // 0..1 -> m*48
    const int warp_n = wid >> 1;      // 0..3 -> n*64
    const int m0 = blockIdx.x * 96;

    const char* Ab = (const char*)g_ctx + (size_t)m0 * 512;
    const char* Wb = (const char*)(g_w + WOFF_OUT);   // hi chunks 0..3

    float acc[3][8][4];
    #pragma unroll
    for (int i = 0; i < 3; i++)
        #pragma unroll
        for (int j = 0; j < 8; j++)
            #pragma unroll
            for (int q = 0; q < 4; q++) acc[i][j][q] = 0.f;

    const int a_mi = lane >> 3;
    const int a_row_base = ((a_mi & 1) << 3) + (lane & 7);
    const int a_kb_sel = (lane >> 4) << 4;
    const int b_row_base = ((a_mi >> 1) << 3) + (lane & 7);
    const int b_kb_sel = ((lane >> 3) & 1) << 4;

    #pragma unroll
    for (int c = 0; c < 4; c++)
        load_tile<96, 512>(base + c * 12288, Ab + c * 128);
    asm volatile("cp.async.commit_group;");
    load_tile<256, 1024>(wbase, Wb);
    asm volatile("cp.async.commit_group;");

    #pragma unroll
    for (int kc = 0; kc < 4; kc++) {
        if (kc + 1 < 4) {
            load_tile<256, 1024>(wbase + ((kc + 1) & 1) * 32768, Wb + (kc + 1) * 128);
            asm volatile("cp.async.commit_group;");
            asm volatile("cp.async.wait_group 1;");
        } else {
            asm volatile("cp.async.wait_group 0;");
        }
        __syncthreads();

        const u32 As = base + kc * 12288;
        const u32 Bs = wbase + (kc & 1) * 32768;
        #pragma unroll
        for (int ks = 0; ks < 4; ks++) {
            u32 a[3][4];
            #pragma unroll
            for (int fm = 0; fm < 3; fm++) {
                int row = warp_m * 48 + fm * 16 + a_row_base;
                u32 kb = (u32)(ks * 32 + a_kb_sel);
                u32 ad = As + row * 128 + (kb ^ ((row & 7) << 4));
                ldsm4(ad, a[fm][0], a[fm][1], a[fm][2], a[fm][3]);
            }
            u32 b[4][4];
            #pragma unroll
            for (int fn = 0; fn < 4; fn++) {
                int row = warp_n * 64 + fn * 16 + b_row_base;
                u32 kb = (u32)(ks * 32 + b_kb_sel);
                u32 bd = Bs + row * 128 + (kb ^ ((row & 7) << 4));
                ldsm4(bd, b[fn][0], b[fn][1], b[fn][2], b[fn][3]);
            }
            #pragma unroll
            for (int fm = 0; fm < 3; fm++)
                #pragma unroll
                for (int f8 = 0; f8 < 8; f8++)
                    mma16816(acc[fm][f8], a[fm],
                             b[f8 >> 1][(f8 & 1) * 2], b[f8 >> 1][(f8 & 1) * 2 + 1]);
        }
        __syncthreads();
    }

    // phase A: cooperative coalesced feature load -> f_s
    float* x_s = (float*)dbase;            // [96][256] fp32
    float* f_s = x_s + 96 * 256;           // [96][256] fp32
    #pragma unroll
    for (int i = 0; i < 24; i++) {
        int idx = i * 256 + tid;           // 6144 float4 units
        int r = idx >> 6, u = idx & 63;
        int m = m0 + r;
        int b = m / 3, t = m - 3 * b;
        const float* src = ((t == 0) ? s0 : (t == 1) ? s1 : s2)
                           + (size_t)b * 256 + u * 4;
        *(float4*)&f_s[r * 256 + u * 4] = *(const float4*)src;
    }
    __syncthreads();

    // phase B: x = acc + bias + feat -> x_s
    const int quad = lane >> 2, tq = lane & 3;
    #pragma unroll
    for (int fm = 0; fm < 3; fm++) {
        const int r0 = warp_m * 48 + fm * 16 + quad;
        #pragma unroll
        for (int f8 = 0; f8 < 8; f8++) {
            const int n = warp_n * 64 + f8 * 8 + 2 * tq;
            float2 bv = *(const float2*)&s_bias[n];
            #pragma unroll
            for (int wh = 0; wh < 2; wh++) {
                int row = r0 + wh * 8;
                float2 ft = *(const float2*)&f_s[row * 256 + n];
                float2 xv = {acc[fm][f8][wh * 2]     + bv.x + ft.x,
                             acc[fm][f8][wh * 2 + 1] + bv.y + ft.y};
                *(float2*)&x_s[row * 256 + n] = xv;
            }
        }
    }
    __syncthreads();

    // phase C: per warp, 4 batches: LN1 x3, gate, fused, LN2, split
    const int d0 = lane * 8;
    #pragma unroll 1
    for (int bl = 0; bl < 4; bl++) {
        int bat = wid * 4 + bl;
        int gbat = m0 / 3 + bat;
        float y[3][8];
        float gpart[3] = {0.f, 0.f, 0.f};
        #pragma unroll
        for (int t = 0; t < 3; t++) {
            int row = bat * 3 + t;
            float x[8];
            *(float4*)&x[0] = *(const float4*)&x_s[row * 256 + d0];
            *(float4*)&x[4] = *(const float4*)&x_s[row * 256 + d0 + 4];
            float s = 0.f;
            #pragma unroll
            for (int j = 0; j < 8; j++) s += x[j];
            s = wsum(s);
            float mu = s * (1.f / 256.f);
            float vv = 0.f;
            #pragma unroll
            for (int j = 0; j < 8; j++) { float d = x[j] - mu; vv += d * d; }
            vv = wsum(vv);
            float rs = rsqrtf(vv * (1.f / 256.f) + 1e-5f);
            #pragma unroll
            for (int j = 0; j < 8; j++)
                y[t][j] = (x[j] - mu) * rs * s_ln[d0 + j] + s_ln[256 + d0 + j];

            float iv[8];
            *(float4*)&iv[0] = *(const float4*)&f_s[row * 256 + d0];
            *(float4*)&iv[4] = *(const float4*)&f_s[row * 256 + d0 + 4];
            #pragma unroll
            for (int g = 0; g < 3; g++) {
                const float* wrow = s_gw + g * 768 + t * 256 + d0;
                #pragma unroll
                for (int j = 0; j < 8; j++) gpart[g] += iv[j] * wrow[j];
            }
        }
        float gl[3];
        #pragma unroll
        for (int g = 0; g < 3; g++) gl[g] = wsum(gpart[g]) + gbias[g];
        float mx = fmaxf(gl[0], fmaxf(gl[1], gl[2]));
        float e0 = expf(gl[0] - mx), e1 = expf(gl[1] - mx), e2 = expf(gl[2] - mx);
        float inv = 1.f / (e0 + e1 + e2);
        float w0 = e0 * inv, w1 = e1 * inv, w2 = e2 * inv;

        float f[8];
        #pragma unroll
        for (int j = 0; j < 8; j++)
            f[j] = w0 * y[0][j] + w1 * y[1][j] + w2 * y[2][j];
        if (out_fused) {
            float* orow = out_fused + (size_t)gbat * 256 + d0;
            *(float4*)orow       = *(float4*)&f[0];
            *(float4*)(orow + 4) = *(float4*)&f[4];
        }
        float s2v = 0.f;
        #pragma unroll
        for (int j = 0; j < 8; j++) s2v += f[j];
        s2v = wsum(s2v);
        float mu2 = s2v * (1.f / 256.f);
        float vv2 = 0.f;
        #pragma unroll
        for (int j = 0; j < 8; j++) { float d = f[j] - mu2; vv2 += d * d; }
        vv2 = wsum(vv2);
        float rs2 = rsqrtf(vv2 * (1.f / 256.f) + 1e-5f);
        u32 hi[4], lo[4];
        #pragma unroll
        for (int j = 0; j < 8; j += 2) {
            float h0 = (f[j]   - mu2) * rs2 * s_ln[512 + d0 + j]   + s_ln[768 + d0 + j];
            float h1 = (f[j+1] - mu2) * rs2 * s_ln[512 + d0 + j+1] + s_ln[768 + d0 + j+1];
            split2(h0, h1, hi[j >> 1], lo[j >> 1]);
        }
        __nv_bfloat16* hrow = g_hh + (size_t)gbat * 512 + d0;
        *(uint4*)hrow         = *(uint4*)hi;
        *(uint4*)(hrow + 256) = *(uint4*)lo;
    }
}

// ---------------------------------------------------------------------------
extern "C" void kernel_launch(void* const* d_in, const int* in_sizes, int n_in,
                              void* d_out, int out_size)
{
    const float* f_swin    = (const float*)d_in[0];
    const float* f_maxvit  = (const float*)d_in[1];
    const float* f_focal   = (const float*)d_in[2];
    const float* in_proj_w = (const float*)d_in[3];
    const float* in_proj_b = (const float*)d_in[4];
    const float* out_w  = (const float*)d_in[5];
    const float* out_b  = (const float*)d_in[6];
    const float* ln1_g  = (const float*)d_in[7];
    const float* ln1_b  = (const float*)d_in[8];
    const float* gate_w = (const float*)d_in[9];
    const float* gate_b = (const float*)d_in[10];
    const float* ln2_g  = (const float*)d_in[11];
    const float* ln2_b  = (const float*)d_in[12];
    const float* w1 = (const float*)d_in[13];
    const float* b1 = (const float*)d_in[14];
    const float* w2 = (const float*)d_in[15];
    const float* b2 = (const float*)d_in[16];
    const float* w3 = (const float*)d_in[17];
    const float* b3 = (const float*)d_in[18];

    int B = in_sizes[0] / 256;
    if (B > BMAX) B = BMAX;
    int rows3 = 3 * B;

    float* outp = (float*)d_out;
    float* out_logits = outp;
    float* out_fused = (out_size >= B * 263) ? (outp + (size_t)B * 7) : nullptr;

    const int SMEM0 = 4 * 16384 + 2 * 16384 + 1024;    // 99 KB
    const int SMEM23 = 8 * 16384 + 2 * 16384 + 1024;   // 165 KB
    const int SMEMF = 2 * 96 * 256 * 4 + 1024;         // 193 KB
    cudaFuncSetAttribute(gemm_mma<0>, cudaFuncAttributeMaxDynamicSharedMemorySize, SMEM0);
    cudaFuncSetAttribute(gemm_mma<2>, cudaFuncAttributeMaxDynamicSharedMemorySize, SMEM23);
    cudaFuncSetAttribute(gemm_mma<3>, cudaFuncAttributeMaxDynamicSharedMemorySize, SMEM23);
    cudaFuncSetAttribute(gemm_fuse, cudaFuncAttributeMaxDynamicSharedMemorySize, SMEMF);

    dim3 blk(256);

    // weight conversion (single launch)
    conv_w_all<<<352, blk>>>(in_proj_w, out_w, w1, w2);

    // qkv GEMM [3B, 768]: fp32 features loaded directly
    gemm_mma<0><<<dim3(6, rows3 / 128), blk, SMEM0>>>(
        in_proj_b, f_swin, f_maxvit, f_focal, nullptr, nullptr, nullptr);
    // attention
    attn_k<<<(B + 7) / 8, blk>>>(B);
    // out-proj + residual + LN1 + gate + fuse + LN2  (one kernel)
    gemm_fuse<<<rows3 / 96, blk, SMEMF>>>(
        out_b, f_swin, f_maxvit, f_focal,
        ln1_g, ln1_b, gate_w, gate_b, ln2_g, ln2_b, out_fused);
    // deep head
    gemm_mma<2><<<dim3(2, B / 128), blk, SMEM23>>>(
        b1, nullptr, nullptr, nullptr, nullptr, nullptr, nullptr);
    gemm_mma<3><<<dim3(1, B / 128), blk, SMEM23>>>(
        b2, nullptr, nullptr, nullptr, w3, b3, out_logits);
}

// round 7
// speedup vs baseline: 1.2003x; 1.2003x over previous
#include <cuda_runtime.h>
#include <cuda_bf16.h>
#include <math.h>
#include <stdint.h>

typedef unsigned int u32;
typedef unsigned long long u64;

#define BMAX 65536

// ---------------------------------------------------------------------------
// Device scratch.
//  g_qkv : qkv bf16                  [3B, 768]
//  g_ctx : attention ctx bf16 single [3B, 256]
//  g_x   : att_out + residual fp32   [3B, 256]
//  g_hh  : LN2(fused) split bf16     [B, 512]  (hi | lo)
//  g_h2  : GELU(h@w1) split bf16     [B, 512]
//  g_w   : split weights             [rows, 512]
// ---------------------------------------------------------------------------
__device__ __nv_bfloat16 g_qkv[(size_t)BMAX * 3 * 768];
__device__ __nv_bfloat16 g_ctx[(size_t)BMAX * 3 * 256];
__device__ float         g_x  [(size_t)BMAX * 3 * 256];
__device__ __nv_bfloat16 g_hh [(size_t)BMAX * 512];
__device__ __nv_bfloat16 g_h2 [(size_t)BMAX * 512];
__device__ __nv_bfloat16 g_w  [(size_t)(768 + 256 + 256 + 128) * 512];

#define WOFF_QKV 0
#define WOFF_OUT (768 * 512)
#define WOFF_W1  ((768 + 256) * 512)
#define WOFF_W2  ((768 + 512) * 512)

__device__ __forceinline__ u32 smem_u32(const void* p) {
    u32 a;
    asm("{ .reg .u64 t; cvta.to.shared.u64 t, %1; cvt.u32.u64 %0, t; }" : "=r"(a) : "l"(p));
    return a;
}
__device__ __forceinline__ float geluf(float x) {
    return 0.5f * x * (1.0f + erff(x * 0.7071067811865476f));
}
__device__ __forceinline__ float wsum(float v) {
    #pragma unroll
    for (int o = 16; o > 0; o >>= 1) v += __shfl_xor_sync(0xffffffffu, v, o);
    return v;
}
__device__ __forceinline__ u32 bf2bits(__nv_bfloat162 h) {
    return *reinterpret_cast<u32*>(&h);
}
__device__ __forceinline__ void split2(float a, float b, u32& h, u32& l) {
    __nv_bfloat162 hh = __floats2bfloat162_rn(a, b);
    float ra = a - __bfloat162float(hh.x);
    float rb = b - __bfloat162float(hh.y);
    __nv_bfloat162 ll = __floats2bfloat162_rn(ra, rb);
    h = bf2bits(hh);
    l = bf2bits(ll);
}

// ---------------------------------------------------------------------------
// merged weight conversion: fp32 [rows,256] -> split bf16 [rows,512]
// ---------------------------------------------------------------------------
__global__ __launch_bounds__(256)
void conv_w_all(const float* __restrict__ ipw, const float* __restrict__ ow,
                const float* __restrict__ w1, const float* __restrict__ w2)
{
    int id = blockIdx.x * 256 + threadIdx.x;     // 1408*64 total
    int row = id >> 6;
    int k = (id & 63) << 2;
    const float* src; int r, woff;
    if (row < 768)       { src = ipw; r = row;        woff = WOFF_QKV; }
    else if (row < 1024) { src = ow;  r = row - 768;  woff = WOFF_OUT; }
    else if (row < 1280) { src = w1;  r = row - 1024; woff = WOFF_W1; }
    else                 { src = w2;  r = row - 1280; woff = WOFF_W2; }
    float4 v = *(const float4*)(src + (size_t)r * 256 + k);
    u32 h0, l0, h1, l1;
    split2(v.x, v.y, h0, l0);
    split2(v.z, v.w, h1, l1);
    __nv_bfloat16* dst = g_w + (size_t)woff + (size_t)r * 512;
    u32* hp = (u32*)(dst + k);
    u32* lp = (u32*)(dst + 256 + k);
    hp[0] = h0; hp[1] = h1;
    lp[0] = l0; lp[1] = l1;
}

// ---------------------------------------------------------------------------
// MMA helpers
// ---------------------------------------------------------------------------
__device__ __forceinline__ void ldsm4(u32 addr, u32& r0, u32& r1, u32& r2, u32& r3) {
    asm volatile("ldmatrix.sync.aligned.m8n8.x4.shared.b16 {%0,%1,%2,%3}, [%4];"
                 : "=r"(r0), "=r"(r1), "=r"(r2), "=r"(r3) : "r"(addr));
}
__device__ __forceinline__ void mma16816(float* c, const u32* a, u32 b0, u32 b1) {
    asm volatile(
        "mma.sync.aligned.m16n8k16.row.col.f32.bf16.bf16.f32 "
        "{%0,%1,%2,%3}, {%4,%5,%6,%7}, {%8,%9}, {%0,%1,%2,%3};"
        : "+f"(c[0]), "+f"(c[1]), "+f"(c[2]), "+f"(c[3])
        : "r"(a[0]), "r"(a[1]), "r"(a[2]), "r"(a[3]), "r"(b0), "r"(b1));
}

// load 128 rows x 128B chunk into SW128-swizzled smem via cp.async
template<int ROWB>
__device__ __forceinline__ void load_tile(u32 sbase, const char* gb) {
    int tid = threadIdx.x;
    #pragma unroll
    for (int i = 0; i < 4; i++) {
        int seg = i * 256 + tid;
        int r = seg >> 3, c = seg & 7;
        u32 off = (u32)(r * 128 + c * 16);
        off ^= (off >> 3) & 0x70;
        asm volatile("cp.async.cg.shared.global [%0], [%1], 16;"
                     :: "r"(sbase + off), "l"(gb + (size_t)r * ROWB + c * 16));
    }
}

// A from fp32 features (direct convert): chunk c (64 floats per row)
__device__ __forceinline__ void load_Afeat(u32 sbase, int m0, int c,
                                           const float* __restrict__ s0,
                                           const float* __restrict__ s1,
                                           const float* __restrict__ s2)
{
    int tid = threadIdx.x;
    #pragma unroll
    for (int i = 0; i < 4; i++) {
        int seg = i * 256 + tid;
        int r = seg >> 3, c8 = seg & 7;
        int m = m0 + r;
        int b = m / 3, t = m - 3 * b;
        const float* src = ((t == 0) ? s0 : (t == 1) ? s1 : s2)
                           + (size_t)b * 256 + c * 64 + c8 * 8;
        float4 v0 = *(const float4*)src;
        float4 v1 = *(const float4*)(src + 4);
        u32 w0 = bf2bits(__floats2bfloat162_rn(v0.x, v0.y));
        u32 w1 = bf2bits(__floats2bfloat162_rn(v0.z, v0.w));
        u32 w2 = bf2bits(__floats2bfloat162_rn(v1.x, v1.y));
        u32 w3 = bf2bits(__floats2bfloat162_rn(v1.z, v1.w));
        u32 off = (u32)(r * 128 + c8 * 16);
        off ^= (off >> 3) & 0x70;
        asm volatile("st.shared.v4.b32 [%0], {%1,%2,%3,%4};"
                     :: "r"(sbase + off), "r"(w0), "r"(w1), "r"(w2), "r"(w3));
    }
}

// ---------------------------------------------------------------------------
// gemm_mma: 128x128 tile GEMMs, resident A, streamed W.
// MODE 0: A = features fp32->bf16, W=in_proj HI only (NP=4) -> g_qkv bf16
// MODE 1: A = g_ctx bf16, W=out_w HI only (NP=4), +bias+residual -> g_x fp32
// MODE 2: A = g_hh split (NP=12), +bias GELU split -> g_h2
// MODE 3: A = g_h2 split (NP=12), +bias GELU -> smem -> fused logits
// ---------------------------------------------------------------------------
template<int MODE>
__global__ __launch_bounds__(256)
void gemm_mma(const float* __restrict__ bias,
              const float* __restrict__ p0, const float* __restrict__ p1,
              const float* __restrict__ p2,
              const float* __restrict__ w3p, const float* __restrict__ b3p,
              float* __restrict__ outp)
{
    constexpr int NP   = (MODE <= 1) ? 4 : 12;
    constexpr int NCHA = (MODE <= 1) ? 4 : 8;
    constexpr int AROW = (MODE == 1) ? 512 : 1024;   // g_ctx rows: 512 B

    extern __shared__ char dsm[];
    char* dbase = (char*)((((uintptr_t)dsm) + 1023) & ~(uintptr_t)1023);
    u32 base = smem_u32(dbase);
    const u32 wbase = base + NCHA * 16384;

    __shared__ float s_w3[896];
    __shared__ float s_b3[8];
    if constexpr (MODE == 3) {
        for (int i = threadIdx.x; i < 896; i += 256) s_w3[i] = w3p[i];
        if (threadIdx.x < 7) s_b3[threadIdx.x] = b3p[threadIdx.x];
    }

    const int tid = threadIdx.x;
    const int lane = tid & 31;
    const int wid = tid >> 5;
    const int warp_m = wid & 3;
    const int warp_n = wid >> 2;

    const int n0 = blockIdx.x * 128;
    const int m0 = blockIdx.y * 128;

    const __nv_bfloat16* Ap = nullptr;
    const __nv_bfloat16* Wp;
    if constexpr (MODE == 0)      {              Wp = g_w + WOFF_QKV; }
    else if constexpr (MODE == 1) { Ap = g_ctx;  Wp = g_w + WOFF_OUT; }
    else if constexpr (MODE == 2) { Ap = g_hh;   Wp = g_w + WOFF_W1; }
    else                          { Ap = g_h2;   Wp = g_w + WOFF_W2; }

    const char* Ab = (const char*)Ap + (size_t)m0 * AROW;
    const char* Wb = (const char*)Wp + (size_t)n0 * 1024;

    const int a_idx12[12] = {0,1,2,3, 0,1,2,3, 4,5,6,7};
    const int w_idx12[12] = {0,1,2,3, 4,5,6,7, 0,1,2,3};

    float acc[2][8][4];
    #pragma unroll
    for (int i = 0; i < 2; i++)
        #pragma unroll
        for (int j = 0; j < 8; j++)
            #pragma unroll
            for (int q = 0; q < 4; q++) acc[i][j][q] = 0.f;

    const int a_mi = lane >> 3;
    const int a_row_base = ((a_mi & 1) << 3) + (lane & 7);
    const int a_kb_sel = (lane >> 4) << 4;
    const int b_row_base = ((a_mi >> 1) << 3) + (lane & 7);
    const int b_kb_sel = ((lane >> 3) & 1) << 4;

    // W prologue + resident A
    load_tile<1024>(wbase, Wb);
    if constexpr (MODE == 0) {
        asm volatile("cp.async.commit_group;");
        #pragma unroll
        for (int c = 0; c < 4; c++)
            load_Afeat(base + c * 16384, m0, c, p0, p1, p2);
    } else {
        #pragma unroll
        for (int c = 0; c < NCHA; c++)
            load_tile<AROW>(base + c * 16384, Ab + c * 128);
        asm volatile("cp.async.commit_group;");
    }

    #pragma unroll
    for (int kc = 0; kc < NP; kc++) {
        const int ai = (MODE <= 1) ? kc : a_idx12[kc];
        if (kc + 1 < NP) {
            const int wi = (MODE <= 1) ? (kc + 1) : w_idx12[kc + 1];
            load_tile<1024>(wbase + ((kc + 1) & 1) * 16384, Wb + wi * 128);
            asm volatile("cp.async.commit_group;");
            asm volatile("cp.async.wait_group 1;");
        } else {
            asm volatile("cp.async.wait_group 0;");
        }
        __syncthreads();

        const u32 As = base + ai * 16384;
        const u32 Bs = wbase + (kc & 1) * 16384;
        #pragma unroll
        for (int ks = 0; ks < 4; ks++) {
            u32 a[2][4];
            #pragma unroll
            for (int fm = 0; fm < 2; fm++) {
                int row = warp_m * 32 + fm * 16 + a_row_base;
                u32 kb = (u32)(ks * 32 + a_kb_sel);
                u32 ad = As + row * 128 + (kb ^ ((row & 7) << 4));
                ldsm4(ad, a[fm][0], a[fm][1], a[fm][2], a[fm][3]);
            }
            u32 b[4][4];
            #pragma unroll
            for (int fn = 0; fn < 4; fn++) {
                int row = warp_n * 64 + fn * 16 + b_row_base;
                u32 kb = (u32)(ks * 32 + b_kb_sel);
                u32 bd = Bs + row * 128 + (kb ^ ((row & 7) << 4));
                ldsm4(bd, b[fn][0], b[fn][1], b[fn][2], b[fn][3]);
            }
            #pragma unroll
            for (int fm = 0; fm < 2; fm++)
                #pragma unroll
                for (int f8 = 0; f8 < 8; f8++)
                    mma16816(acc[fm][f8], a[fm],
                             b[f8 >> 1][(f8 & 1) * 2], b[f8 >> 1][(f8 & 1) * 2 + 1]);
        }
        __syncthreads();
    }

    // ------------------------- epilogue -------------------------
    const int quad = lane >> 2, tq = lane & 3;
    float* h3_s = (float*)dbase;    // MODE 3: [128][128] fp32 (A region dead)

    #pragma unroll
    for (int fm = 0; fm < 2; fm++) {
        const int mA = m0 + warp_m * 32 + fm * 16 + quad;
        const float* resA = nullptr; const float* resB = nullptr;
        if constexpr (MODE == 1) {
            int ba = mA / 3, ta = mA - ba * 3;
            resA = ((ta == 0) ? p0 : (ta == 1) ? p1 : p2) + (size_t)ba * 256;
            int mB = mA + 8;
            int bb = mB / 3, tb = mB - bb * 3;
            resB = ((tb == 0) ? p0 : (tb == 1) ? p1 : p2) + (size_t)bb * 256;
        }
        #pragma unroll
        for (int f8 = 0; f8 < 8; f8++) {
            const int n = n0 + warp_n * 64 + f8 * 8 + 2 * tq;
            float2 bv = *(const float2*)&bias[n];
            float v0 = acc[fm][f8][0] + bv.x;
            float v1 = acc[fm][f8][1] + bv.y;
            float v2 = acc[fm][f8][2] + bv.x;
            float v3 = acc[fm][f8][3] + bv.y;
            if constexpr (MODE == 0) {
                *(u32*)&g_qkv[(size_t)mA * 768 + n]       = bf2bits(__floats2bfloat162_rn(v0, v1));
                *(u32*)&g_qkv[(size_t)(mA + 8) * 768 + n] = bf2bits(__floats2bfloat162_rn(v2, v3));
            } else if constexpr (MODE == 1) {
                float2 r0 = *(const float2*)&resA[n];
                float2 r1 = *(const float2*)&resB[n];
                *(float2*)&g_x[(size_t)mA * 256 + n]       = {v0 + r0.x, v1 + r0.y};
                *(float2*)&g_x[(size_t)(mA + 8) * 256 + n] = {v2 + r1.x, v3 + r1.y};
            } else if constexpr (MODE == 2) {
                u32 h0, l0, h1, l1;
                split2(geluf(v0), geluf(v1), h0, l0);
                split2(geluf(v2), geluf(v3), h1, l1);
                *(u32*)&g_h2[(size_t)mA * 512 + n]             = h0;
                *(u32*)&g_h2[(size_t)mA * 512 + 256 + n]       = l0;
                *(u32*)&g_h2[(size_t)(mA + 8) * 512 + n]       = h1;
                *(u32*)&g_h2[(size_t)(mA + 8) * 512 + 256 + n] = l1;
            } else {
                int rl = warp_m * 32 + fm * 16 + quad;
                *(float2*)&h3_s[rl * 128 + n]       = {geluf(v0), geluf(v1)};
                *(float2*)&h3_s[(rl + 8) * 128 + n] = {geluf(v2), geluf(v3)};
            }
        }
    }

    if constexpr (MODE == 3) {
        __syncthreads();
        const int d0 = lane * 4;
        float4 wv[7];
        #pragma unroll
        for (int j = 0; j < 7; j++) wv[j] = *(const float4*)&s_w3[j * 128 + d0];
        #pragma unroll 1
        for (int rr = 0; rr < 16; rr++) {
            int row = wid * 16 + rr;
            float4 h = *(const float4*)&h3_s[row * 128 + d0];
            float r[7];
            #pragma unroll
            for (int j = 0; j < 7; j++) {
                float p = h.x * wv[j].x + h.y * wv[j].y + h.z * wv[j].z + h.w * wv[j].w;
                r[j] = wsum(p);
            }
            if (lane == 0) {
                #pragma unroll
                for (int j = 0; j < 7; j++)
                    outp[(size_t)(m0 + row) * 7 + j] = r[j] + s_b3[j];
            }
        }
    }
}

// ---------------------------------------------------------------------------
// attention: warp per batch row; reads bf16 qkv, writes ctx bf16 single
// ---------------------------------------------------------------------------
__global__ __launch_bounds__(256)
void attn_k(int B)
{
    int warp = threadIdx.x >> 5, lane = threadIdx.x & 31;
    int b = blockIdx.x * 8 + warp;
    if (b >= B) return;
    int d0 = lane * 8;

    float q[3][8], k[3][8], v[3][8];
    #pragma unroll
    for (int t = 0; t < 3; t++) {
        const __nv_bfloat16* row = g_qkv + ((size_t)b * 3 + t) * 768;
        uint4 qr = *(const uint4*)(row + d0);
        uint4 kr = *(const uint4*)(row + 256 + d0);
        uint4 vr = *(const uint4*)(row + 512 + d0);
        const u32* qw = (const u32*)&qr;
        const u32* kw = (const u32*)&kr;
        const u32* vw = (const u32*)&vr;
        #pragma unroll
        for (int j = 0; j < 4; j++) {
            float2 qf = __bfloat1622float2(*(const __nv_bfloat162*)&qw[j]);
            float2 kf = __bfloat1622float2(*(const __nv_bfloat162*)&kw[j]);
            float2 vf = __bfloat1622float2(*(const __nv_bfloat162*)&vw[j]);
            q[t][2*j] = qf.x; q[t][2*j+1] = qf.y;
            k[t][2*j] = kf.x; k[t][2*j+1] = kf.y;
            v[t][2*j] = vf.x; v[t][2*j+1] = vf.y;
        }
    }
    float s[3][3];
    #pragma unroll
    for (int t = 0; t < 3; t++)
        #pragma unroll
        for (int u = 0; u < 3; u++) {
            float p = 0.f;
            #pragma unroll
            for (int j = 0; j < 8; j++) p += q[t][j] * k[u][j];
            p += __shfl_xor_sync(0xffffffffu, p, 1);
            p += __shfl_xor_sync(0xffffffffu, p, 2);
            p += __shfl_xor_sync(0xffffffffu, p, 4);
            s[t][u] = p * 0.125f;
        }
    #pragma unroll
    for (int t = 0; t < 3; t++) {
        float mx = fmaxf(s[t][0], fmaxf(s[t][1], s[t][2]));
        float e0 = expf(s[t][0] - mx);
        float e1 = expf(s[t][1] - mx);
        float e2 = expf(s[t][2] - mx);
        float inv = 1.f / (e0 + e1 + e2);
        u32 cw[4];
        #pragma unroll
        for (int j = 0; j < 8; j += 2) {
            float c0 = (e0 * v[0][j]   + e1 * v[1][j]   + e2 * v[2][j])   * inv;
            float c1 = (e0 * v[0][j+1] + e1 * v[1][j+1] + e2 * v[2][j+1]) * inv;
            cw[j >> 1] = bf2bits(__floats2bfloat162_rn(c0, c1));
        }
        *(uint4*)(g_ctx + ((size_t)b * 3 + t) * 256 + d0) = *(uint4*)cw;
    }
}

// ---------------------------------------------------------------------------
// fuse: LN1 per token, gate softmax, fused (fp32), LN2 -> g_hh (split).
// Params cached in smem; grid-stride over tokens.
// ---------------------------------------------------------------------------
__global__ __launch_bounds__(256)
void fuse_k(const float* __restrict__ s0, const float* __restrict__ s1,
            const float* __restrict__ s2,
            const float* __restrict__ ln1g, const float* __restrict__ ln1b,
            const float* __restrict__ gw,   const float* __restrict__ gb,
            const float* __restrict__ ln2g, const float* __restrict__ ln2b,
            float* __restrict__ out_fused, int B)
{
    __shared__ float s_gw[2304];
    __shared__ float s_ln[1024];
    for (int i = threadIdx.x; i < 2304; i += 256) s_gw[i] = gw[i];
    if (threadIdx.x < 256) {
        int i = threadIdx.x;
        s_ln[i]       = ln1g[i];
        s_ln[256 + i] = ln1b[i];
        s_ln[512 + i] = ln2g[i];
        s_ln[768 + i] = ln2b[i];
    }
    __syncthreads();

    int warp = threadIdx.x >> 5, lane = threadIdx.x & 31;
    int d0 = lane * 8;
    const float* srcs[3] = {s0, s1, s2};

    for (int b = blockIdx.x * 8 + warp; b < B; b += gridDim.x * 8) {
        float y[3][8];
        float gpart[3] = {0.f, 0.f, 0.f};
        #pragma unroll
        for (int t = 0; t < 3; t++) {
            float x[8];
            const float* row = g_x + ((size_t)b * 3 + t) * 256;
            *(float4*)&x[0] = *(const float4*)(row + d0);
            *(float4*)&x[4] = *(const float4*)(row + d0 + 4);
            float s = 0.f;
            #pragma unroll
            for (int j = 0; j < 8; j++) s += x[j];
            s = wsum(s);
            float mu = s * (1.f / 256.f);
            float vv = 0.f;
            #pragma unroll
            for (int j = 0; j < 8; j++) { float d = x[j] - mu; vv += d * d; }
            vv = wsum(vv);
            float rs = rsqrtf(vv * (1.f / 256.f) + 1e-5f);
            #pragma unroll
            for (int j = 0; j < 8; j++)
                y[t][j] = (x[j] - mu) * rs * s_ln[d0 + j] + s_ln[256 + d0 + j];

            float iv[8];
            const float* in = srcs[t] + (size_t)b * 256;
            *(float4*)&iv[0] = *(const float4*)(in + d0);
            *(float4*)&iv[4] = *(const float4*)(in + d0 + 4);
            #pragma unroll
            for (int g = 0; g < 3; g++) {
                const float* wrow = s_gw + g * 768 + t * 256 + d0;
                #pragma unroll
                for (int j = 0; j < 8; j++) gpart[g] += iv[j] * wrow[j];
            }
        }
        float gl[3];
        #pragma unroll
        for (int g = 0; g < 3; g++) gl[g] = wsum(gpart[g]) + gb[g];
        float mx = fmaxf(gl[0], fmaxf(gl[1], gl[2]));
        float e0 = expf(gl[0] - mx), e1 = expf(gl[1] - mx), e2 = expf(gl[2] - mx);
        float inv = 1.f / (e0 + e1 + e2);
        float w0 = e0 * inv, w1 = e1 * inv, w2 = e2 * inv;

        float f[8];
        #pragma unroll
        for (int j = 0; j < 8; j++)
            f[j] = w0 * y[0][j] + w1 * y[1][j] + w2 * y[2][j];
        if (out_fused) {
            float* orow = out_fused + (size_t)b * 256 + d0;
            *(float4*)orow       = *(float4*)&f[0];
            *(float4*)(orow + 4) = *(float4*)&f[4];
        }
        float s2v = 0.f;
        #pragma unroll
        for (int j = 0; j < 8; j++) s2v += f[j];
        s2v = wsum(s2v);
        float mu2 = s2v * (1.f / 256.f);
        float vv2 = 0.f;
        #pragma unroll
        for (int j = 0; j < 8; j++) { float d = f[j] - mu2; vv2 += d * d; }
        vv2 = wsum(vv2);
        float rs2 = rsqrtf(vv2 * (1.f / 256.f) + 1e-5f);
        u32 hi[4], lo[4];
        #pragma unroll
        for (int j = 0; j < 8; j += 2) {
            float h0 = (f[j]   - mu2) * rs2 * s_ln[512 + d0 + j]   + s_ln[768 + d0 + j];
            float h1 = (f[j+1] - mu2) * rs2 * s_ln[512 + d0 + j+1] + s_ln[768 + d0 + j+1];
            split2(h0, h1, hi[j >> 1], lo[j >> 1]);
        }
        __nv_bfloat16* hrow = g_hh + (size_t)b * 512 + d0;
        *(uint4*)hrow         = *(uint4*)hi;
        *(uint4*)(hrow + 256) = *(uint4*)lo;
    }
}

// ---------------------------------------------------------------------------
extern "C" void kernel_launch(void* const* d_in, const int* in_sizes, int n_in,
                              void* d_out, int out_size)
{
    const float* f_swin    = (const float*)d_in[0];
    const float* f_maxvit  = (const float*)d_in[1];
    const float* f_focal   = (const float*)d_in[2];
    const float* in_proj_w = (const float*)d_in[3];
    const float* in_proj_b = (const float*)d_in[4];
    const float* out_w  = (const float*)d_in[5];
    const float* out_b  = (const float*)d_in[6];
    const float* ln1_g  = (const float*)d_in[7];
    const float* ln1_b  = (const float*)d_in[8];
    const float* gate_w = (const float*)d_in[9];
    const float* gate_b = (const float*)d_in[10];
    const float* ln2_g  = (const float*)d_in[11];
    const float* ln2_b  = (const float*)d_in[12];
    const float* w1 = (const float*)d_in[13];
    const float* b1 = (const float*)d_in[14];
    const float* w2 = (const float*)d_in[15];
    const float* b2 = (const float*)d_in[16];
    const float* w3 = (const float*)d_in[17];
    const float* b3 = (const float*)d_in[18];

    int B = in_sizes[0] / 256;
    if (B > BMAX) B = BMAX;
    int rows3 = 3 * B;

    float* outp = (float*)d_out;
    float* out_logits = outp;
    float* out_fused = (out_size >= B * 263) ? (outp + (size_t)B * 7) : nullptr;

    const int SMEM01 = 4 * 16384 + 2 * 16384 + 1024;   // 99 KB
    const int SMEM23 = 8 * 16384 + 2 * 16384 + 1024;   // 165 KB
    cudaFuncSetAttribute(gemm_mma<0>, cudaFuncAttributeMaxDynamicSharedMemorySize, SMEM01);
    cudaFuncSetAttribute(gemm_mma<1>, cudaFuncAttributeMaxDynamicSharedMemorySize, SMEM01);
    cudaFuncSetAttribute(gemm_mma<2>, cudaFuncAttributeMaxDynamicSharedMemorySize, SMEM23);
    cudaFuncSetAttribute(gemm_mma<3>, cudaFuncAttributeMaxDynamicSharedMemorySize, SMEM23);

    dim3 blk(256);

    // weight conversion (single launch)
    conv_w_all<<<352, blk>>>(in_proj_w, out_w, w1, w2);

    // qkv GEMM [3B, 768]: fp32 features loaded directly, hi weights only
    gemm_mma<0><<<dim3(6, rows3 / 128), blk, SMEM01>>>(
        in_proj_b, f_swin, f_maxvit, f_focal, nullptr, nullptr, nullptr);
    // attention
    attn_k<<<(B + 7) / 8, blk>>>(B);
    // out-proj + residual (hi weights only)
    gemm_mma<1><<<dim3(2, rows3 / 128), blk, SMEM01>>>(
        out_b, f_swin, f_maxvit, f_focal, nullptr, nullptr, nullptr);
    // LN1 + gate + fused + LN2
    fuse_k<<<1024, blk>>>(f_swin, f_maxvit, f_focal,
                          ln1_g, ln1_b, gate_w, gate_b, ln2_g, ln2_b,
                          out_fused, B);
    // deep head (full split precision); logits fused into MODE 3 epilogue
    gemm_mma<2><<<dim3(2, B / 128), blk, SMEM23>>>(
        b1, nullptr, nullptr, nullptr, nullptr, nullptr, nullptr);
    gemm_mma<3><<<dim3(1, B / 128), blk, SMEM23>>>(
        b2, nullptr, nullptr, nullptr, w3, b3, out_logits);
}

// round 8
// speedup vs baseline: 1.2992x; 1.0824x over previous
#include <cuda_runtime.h>
#include <cuda_bf16.h>
#include <math.h>
#include <stdint.h>

typedef unsigned int u32;
typedef unsigned long long u64;

#define BMAX 65536

// ---------------------------------------------------------------------------
// Device scratch.
//  g_ctx : attention ctx bf16 single [3B, 256]
//  g_x   : att_out + residual fp32   [3B, 256]
//  g_hh  : LN2(fused) split bf16     [B, 512]  (hi | lo)
//  g_w   : split weights             [rows, 512]
// ---------------------------------------------------------------------------
__device__ __nv_bfloat16 g_ctx[(size_t)BMAX * 3 * 256];
__device__ float         g_x  [(size_t)BMAX * 3 * 256];
__device__ __nv_bfloat16 g_hh [(size_t)BMAX * 512];
__device__ __nv_bfloat16 g_w  [(size_t)(768 + 256 + 256 + 128) * 512];

#define WOFF_QKV 0
#define WOFF_OUT (768 * 512)
#define WOFF_W1  ((768 + 256) * 512)
#define WOFF_W2  ((768 + 512) * 512)

__device__ __forceinline__ u32 smem_u32(const void* p) {
    u32 a;
    asm("{ .reg .u64 t; cvta.to.shared.u64 t, %1; cvt.u32.u64 %0, t; }" : "=r"(a) : "l"(p));
    return a;
}
__device__ __forceinline__ float geluf(float x) {
    return 0.5f * x * (1.0f + erff(x * 0.7071067811865476f));
}
__device__ __forceinline__ float wsum(float v) {
    #pragma unroll
    for (int o = 16; o > 0; o >>= 1) v += __shfl_xor_sync(0xffffffffu, v, o);
    return v;
}
__device__ __forceinline__ u32 bf2bits(__nv_bfloat162 h) {
    return *reinterpret_cast<u32*>(&h);
}
__device__ __forceinline__ void split2(float a, float b, u32& h, u32& l) {
    __nv_bfloat162 hh = __floats2bfloat162_rn(a, b);
    float ra = a - __bfloat162float(hh.x);
    float rb = b - __bfloat162float(hh.y);
    __nv_bfloat162 ll = __floats2bfloat162_rn(ra, rb);
    h = bf2bits(hh);
    l = bf2bits(ll);
}

// ---------------------------------------------------------------------------
// merged weight conversion: fp32 [rows,256] -> split bf16 [rows,512]
// ---------------------------------------------------------------------------
__global__ __launch_bounds__(256)
void conv_w_all(const float* __restrict__ ipw, const float* __restrict__ ow,
                const float* __restrict__ w1, const float* __restrict__ w2)
{
    int id = blockIdx.x * 256 + threadIdx.x;
    int row = id >> 6;
    int k = (id & 63) << 2;
    const float* src; int r, woff;
    if (row < 768)       { src = ipw; r = row;        woff = WOFF_QKV; }
    else if (row < 1024) { src = ow;  r = row - 768;  woff = WOFF_OUT; }
    else if (row < 1280) { src = w1;  r = row - 1024; woff = WOFF_W1; }
    else                 { src = w2;  r = row - 1280; woff = WOFF_W2; }
    float4 v = *(const float4*)(src + (size_t)r * 256 + k);
    u32 h0, l0, h1, l1;
    split2(v.x, v.y, h0, l0);
    split2(v.z, v.w, h1, l1);
    __nv_bfloat16* dst = g_w + (size_t)woff + (size_t)r * 512;
    u32* hp = (u32*)(dst + k);
    u32* lp = (u32*)(dst + 256 + k);
    hp[0] = h0; hp[1] = h1;
    lp[0] = l0; lp[1] = l1;
}

// ---------------------------------------------------------------------------
// MMA helpers
// ---------------------------------------------------------------------------
__device__ __forceinline__ void ldsm4(u32 addr, u32& r0, u32& r1, u32& r2, u32& r3) {
    asm volatile("ldmatrix.sync.aligned.m8n8.x4.shared.b16 {%0,%1,%2,%3}, [%4];"
                 : "=r"(r0), "=r"(r1), "=r"(r2), "=r"(r3) : "r"(addr));
}
__device__ __forceinline__ void mma16816(float* c, const u32* a, u32 b0, u32 b1) {
    asm volatile(
        "mma.sync.aligned.m16n8k16.row.col.f32.bf16.bf16.f32 "
        "{%0,%1,%2,%3}, {%4,%5,%6,%7}, {%8,%9}, {%0,%1,%2,%3};"
        : "+f"(c[0]), "+f"(c[1]), "+f"(c[2]), "+f"(c[3])
        : "r"(a[0]), "r"(a[1]), "r"(a[2]), "r"(a[3]), "r"(b0), "r"(b1));
}

// load NROWS x 128B chunk into SW128-swizzled smem via cp.async
template<int NROWS, int ROWB>
__device__ __forceinline__ void load_tile(u32 sbase, const char* gb) {
    constexpr int ITERS = NROWS * 8 / 256;
    int tid = threadIdx.x;
    #pragma unroll
    for (int i = 0; i < ITERS; i++) {
        int seg = i * 256 + tid;
        int r = seg >> 3, c = seg & 7;
        u32 off = (u32)(r * 128 + c * 16);
        off ^= (off >> 3) & 0x70;
        asm volatile("cp.async.cg.shared.global [%0], [%1], 16;"
                     :: "r"(sbase + off), "l"(gb + (size_t)r * ROWB + c * 16));
    }
}

// 96-row feature chunk: fp32 -> bf16 direct into swizzled smem
__device__ __forceinline__ void load_Afeat96(u32 sbase, int m0, int c,
                                             const float* __restrict__ s0,
                                             const float* __restrict__ s1,
                                             const float* __restrict__ s2)
{
    int tid = threadIdx.x;
    #pragma unroll
    for (int i = 0; i < 3; i++) {
        int seg = i * 256 + tid;          // 768 segs of 16B bf16 (=8 floats)
        int r = seg >> 3, c8 = seg & 7;
        int m = m0 + r;
        int b = m / 3, t = m - 3 * b;
        const float* src = ((t == 0) ? s0 : (t == 1) ? s1 : s2)
                           + (size_t)b * 256 + c * 64 + c8 * 8;
        float4 v0 = *(const float4*)src;
        float4 v1 = *(const float4*)(src + 4);
        u32 w0 = bf2bits(__floats2bfloat162_rn(v0.x, v0.y));
        u32 w1 = bf2bits(__floats2bfloat162_rn(v0.z, v0.w));
        u32 w2 = bf2bits(__floats2bfloat162_rn(v1.x, v1.y));
        u32 w3 = bf2bits(__floats2bfloat162_rn(v1.z, v1.w));
        u32 off = (u32)(r * 128 + c8 * 16);
        off ^= (off >> 3) & 0x70;
        asm volatile("st.shared.v4.b32 [%0], {%1,%2,%3,%4};"
                     :: "r"(sbase + off), "r"(w0), "r"(w1), "r"(w2), "r"(w3));
    }
}

// ---------------------------------------------------------------------------
// qkv_attn: fused qkv projection + attention.
//  M_TILE = 96 rows = 32 whole batches. Features resident in smem (bf16),
//  6 n-tiles of W(hi) streamed; qkv parked in smem [96][768] bf16; then
//  per-batch 3x3 attention from smem, writes g_ctx only.
// smem: A 4x12288 (48K) | W 2x16384 (32K) | qkv 147456 (144K) = 224K
// ---------------------------------------------------------------------------
__global__ __launch_bounds__(256)
void qkv_attn(const float* __restrict__ ipb,
              const float* __restrict__ s0, const float* __restrict__ s1,
              const float* __restrict__ s2)
{
    extern __shared__ char dsm[];
    char* dbase = (char*)((((uintptr_t)dsm) + 1023) & ~(uintptr_t)1023);
    u32 base = smem_u32(dbase);
    const u32 wbase = base + 49152;
    char* qkv_s = dbase + 81920;              // [96][768] bf16, row stride 1536B

    const int tid = threadIdx.x;
    const int lane = tid & 31;
    const int wid = tid >> 5;
    const int warp_m = wid & 1;               // 0..1 -> 48 rows
    const int warp_n = wid >> 1;              // 0..3 -> 32 cols
    const int m0 = blockIdx.x * 96;

    const char* Wq = (const char*)(g_w + WOFF_QKV);

    const int a_mi = lane >> 3;
    const int a_row_base = ((a_mi & 1) << 3) + (lane & 7);
    const int a_kb_sel = (lane >> 4) << 4;
    const int b_row_base = ((a_mi >> 1) << 3) + (lane & 7);
    const int b_kb_sel = ((lane >> 3) & 1) << 4;
    const int quad = lane >> 2, tq = lane & 3;

    // W prologue (cp.async group), then resident A via st.shared
    load_tile<128, 1024>(wbase, Wq);          // nt0, chunk0
    asm volatile("cp.async.commit_group;");
    #pragma unroll
    for (int c = 0; c < 4; c++)
        load_Afeat96(base + c * 12288, m0, c, s0, s1, s2);

    #pragma unroll 1
    for (int nt = 0; nt < 6; nt++) {
        float acc[3][4][4];
        #pragma unroll
        for (int i = 0; i < 3; i++)
            #pragma unroll
            for (int j = 0; j < 4; j++)
                #pragma unroll
                for (int q = 0; q < 4; q++) acc[i][j][q] = 0.f;

        #pragma unroll
        for (int kc = 0; kc < 4; kc++) {
            const int gc = nt * 4 + kc;
            if (gc + 1 < 24) {
                const int nnt = (gc + 1) >> 2, nkc = (gc + 1) & 3;
                load_tile<128, 1024>(wbase + ((gc + 1) & 1) * 16384,
                                     Wq + (size_t)nnt * 131072 + nkc * 128);
                asm volatile("cp.async.commit_group;");
                asm volatile("cp.async.wait_group 1;");
            } else {
                asm volatile("cp.async.wait_group 0;");
            }
            __syncthreads();

            const u32 As = base + kc * 12288;
            const u32 Bs = wbase + (gc & 1) * 16384;
            #pragma unroll
            for (int ks = 0; ks < 4; ks++) {
                u32 a[3][4];
                #pragma unroll
                for (int fm = 0; fm < 3; fm++) {
                    int row = warp_m * 48 + fm * 16 + a_row_base;
                    u32 kb = (u32)(ks * 32 + a_kb_sel);
                    u32 ad = As + row * 128 + (kb ^ ((row & 7) << 4));
                    ldsm4(ad, a[fm][0], a[fm][1], a[fm][2], a[fm][3]);
                }
                u32 b[2][4];
                #pragma unroll
                for (int fn = 0; fn < 2; fn++) {
                    int row = warp_n * 32 + fn * 16 + b_row_base;
                    u32 kb = (u32)(ks * 32 + b_kb_sel);
                    u32 bd = Bs + row * 128 + (kb ^ ((row & 7) << 4));
                    ldsm4(bd, b[fn][0], b[fn][1], b[fn][2], b[fn][3]);
                }
                #pragma unroll
                for (int fm = 0; fm < 3; fm++)
                    #pragma unroll
                    for (int f8 = 0; f8 < 4; f8++)
                        mma16816(acc[fm][f8], a[fm],
                                 b[f8 >> 1][(f8 & 1) * 2], b[f8 >> 1][(f8 & 1) * 2 + 1]);
            }
            __syncthreads();
        }

        // park this n-tile's qkv in smem (+bias, bf16)
        #pragma unroll
        for (int fm = 0; fm < 3; fm++) {
            const int r = warp_m * 48 + fm * 16 + quad;
            #pragma unroll
            for (int f8 = 0; f8 < 4; f8++) {
                const int ncol = nt * 128 + warp_n * 32 + f8 * 8 + 2 * tq;
                float2 bv = *(const float2*)&ipb[ncol];
                u32 lo = bf2bits(__floats2bfloat162_rn(acc[fm][f8][0] + bv.x,
                                                       acc[fm][f8][1] + bv.y));
                u32 hi = bf2bits(__floats2bfloat162_rn(acc[fm][f8][2] + bv.x,
                                                       acc[fm][f8][3] + bv.y));
                *(u32*)(qkv_s + (size_t)r * 1536 + ncol * 2)       = lo;
                *(u32*)(qkv_s + (size_t)(r + 8) * 1536 + ncol * 2) = hi;
            }
        }
    }
    __syncthreads();

    // attention from smem: each warp handles 4 batches
    const int d0 = lane * 8;
    #pragma unroll 1
    for (int bl = 0; bl < 4; bl++) {
        int tb = wid * 4 + bl;                 // 0..31 within tile
        int gb = blockIdx.x * 32 + tb;         // global batch

        float q[3][8], k[3][8], v[3][8];
        #pragma unroll
        for (int t = 0; t < 3; t++) {
            const char* rp = qkv_s + (size_t)(tb * 3 + t) * 1536 + d0 * 2;
            uint4 qr = *(const uint4*)rp;
            uint4 kr = *(const uint4*)(rp + 512);
            uint4 vr = *(const uint4*)(rp + 1024);
            const u32* qw = (const u32*)&qr;
            const u32* kw = (const u32*)&kr;
            const u32* vw = (const u32*)&vr;
            #pragma unroll
            for (int j = 0; j < 4; j++) {
                float2 qf = __bfloat1622float2(*(const __nv_bfloat162*)&qw[j]);
                float2 kf = __bfloat1622float2(*(const __nv_bfloat162*)&kw[j]);
                float2 vf = __bfloat1622float2(*(const __nv_bfloat162*)&vw[j]);
                q[t][2*j] = qf.x; q[t][2*j+1] = qf.y;
                k[t][2*j] = kf.x; k[t][2*j+1] = kf.y;
                v[t][2*j] = vf.x; v[t][2*j+1] = vf.y;
            }
        }
        float s[3][3];
        #pragma unroll
        for (int t = 0; t < 3; t++)
            #pragma unroll
            for (int u = 0; u < 3; u++) {
                float p = 0.f;
                #pragma unroll
                for (int j = 0; j < 8; j++) p += q[t][j] * k[u][j];
                p += __shfl_xor_sync(0xffffffffu, p, 1);
                p += __shfl_xor_sync(0xffffffffu, p, 2);
                p += __shfl_xor_sync(0xffffffffu, p, 4);
                s[t][u] = p * 0.125f;
            }
        #pragma unroll
        for (int t = 0; t < 3; t++) {
            float mx = fmaxf(s[t][0], fmaxf(s[t][1], s[t][2]));
            float e0 = expf(s[t][0] - mx);
            float e1 = expf(s[t][1] - mx);
            float e2 = expf(s[t][2] - mx);
            float inv = 1.f / (e0 + e1 + e2);
            u32 cw[4];
            #pragma unroll
            for (int j = 0; j < 8; j += 2) {
                float c0 = (e0 * v[0][j]   + e1 * v[1][j]   + e2 * v[2][j])   * inv;
                float c1 = (e0 * v[0][j+1] + e1 * v[1][j+1] + e2 * v[2][j+1]) * inv;
                cw[j >> 1] = bf2bits(__floats2bfloat162_rn(c0, c1));
            }
            *(uint4*)(g_ctx + ((size_t)gb * 3 + t) * 256 + d0) = *(uint4*)cw;
        }
    }
}

// ---------------------------------------------------------------------------
// gemm_out: out-proj (A=g_ctx bf16, W=out_w hi only NP=4), +bias+residual -> g_x
// 128x128 tile, resident A, streamed W, occ-2 (99KB).
// ---------------------------------------------------------------------------
__global__ __launch_bounds__(256)
void gemm_out(const float* __restrict__ bias,
              const float* __restrict__ p0, const float* __restrict__ p1,
              const float* __restrict__ p2)
{
    extern __shared__ char dsm[];
    char* dbase = (char*)((((uintptr_t)dsm) + 1023) & ~(uintptr_t)1023);
    u32 base = smem_u32(dbase);
    const u32 wbase = base + 4 * 16384;

    const int tid = threadIdx.x;
    const int lane = tid & 31;
    const int wid = tid >> 5;
    const int warp_m = wid & 3;
    const int warp_n = wid >> 2;

    const int n0 = blockIdx.x * 128;
    const int m0 = blockIdx.y * 128;

    const char* Ab = (const char*)g_ctx + (size_t)m0 * 512;
    const char* Wb = (const char*)(g_w + WOFF_OUT) + (size_t)n0 * 1024;

    float acc[2][8][4];
    #pragma unroll
    for (int i = 0; i < 2; i++)
        #pragma unroll
        for (int j = 0; j < 8; j++)
            #pragma unroll
            for (int q = 0; q < 4; q++) acc[i][j][q] = 0.f;

    const int a_mi = lane >> 3;
    const int a_row_base = ((a_mi & 1) << 3) + (lane & 7);
    const int a_kb_sel = (lane >> 4) << 4;
    const int b_row_base = ((a_mi >> 1) << 3) + (lane & 7);
    const int b_kb_sel = ((lane >> 3) & 1) << 4;

    load_tile<128, 1024>(wbase, Wb);
    asm volatile("cp.async.commit_group;");
    #pragma unroll
    for (int c = 0; c < 4; c++)
        load_tile<128, 512>(base + c * 16384, Ab + c * 128);
    asm volatile("cp.async.commit_group;");

    #pragma unroll
    for (int kc = 0; kc < 4; kc++) {
        if (kc + 1 < 4) {
            load_tile<128, 1024>(wbase + ((kc + 1) & 1) * 16384, Wb + (kc + 1) * 128);
            asm volatile("cp.async.commit_group;");
            asm volatile("cp.async.wait_group 1;");
        } else {
            asm volatile("cp.async.wait_group 0;");
        }
        __syncthreads();

        const u32 As = base + kc * 16384;
        const u32 Bs = wbase + (kc & 1) * 16384;
        #pragma unroll
        for (int ks = 0; ks < 4; ks++) {
            u32 a[2][4];
            #pragma unroll
            for (int fm = 0; fm < 2; fm++) {
                int row = warp_m * 32 + fm * 16 + a_row_base;
                u32 kb = (u32)(ks * 32 + a_kb_sel);
                u32 ad = As + row * 128 + (kb ^ ((row & 7) << 4));
                ldsm4(ad, a[fm][0], a[fm][1], a[fm][2], a[fm][3]);
            }
            u32 b[4][4];
            #pragma unroll
            for (int fn = 0; fn < 4; fn++) {
                int row = warp_n * 64 + fn * 16 + b_row_base;
                u32 kb = (u32)(ks * 32 + b_kb_sel);
                u32 bd = Bs + row * 128 + (kb ^ ((row & 7) << 4));
                ldsm4(bd, b[fn][0], b[fn][1], b[fn][2], b[fn][3]);
            }
            #pragma unroll
            for (int fm = 0; fm < 2; fm++)
                #pragma unroll
                for (int f8 = 0; f8 < 8; f8++)
                    mma16816(acc[fm][f8], a[fm],
                             b[f8 >> 1][(f8 & 1) * 2], b[f8 >> 1][(f8 & 1) * 2 + 1]);
        }
        __syncthreads();
    }

    const int quad = lane >> 2, tq = lane & 3;
    #pragma unroll
    for (int fm = 0; fm < 2; fm++) {
        const int mA = m0 + warp_m * 32 + fm * 16 + quad;
        int ba = mA / 3, ta = mA - ba * 3;
        const float* resA = ((ta == 0) ? p0 : (ta == 1) ? p1 : p2) + (size_t)ba * 256;
        int mB = mA + 8;
        int bb = mB / 3, tb = mB - bb * 3;
        const float* resB = ((tb == 0) ? p0 : (tb == 1) ? p1 : p2) + (size_t)bb * 256;
        #pragma unroll
        for (int f8 = 0; f8 < 8; f8++) {
            const int n = n0 + warp_n * 64 + f8 * 8 + 2 * tq;
            float2 bv = *(const float2*)&bias[n];
            float2 r0 = *(const float2*)&resA[n];
            float2 r1 = *(const float2*)&resB[n];
            *(float2*)&g_x[(size_t)mA * 256 + n] =
                {acc[fm][f8][0] + bv.x + r0.x, acc[fm][f8][1] + bv.y + r0.y};
            *(float2*)&g_x[(size_t)(mA + 8) * 256 + n] =
                {acc[fm][f8][2] + bv.x + r1.x, acc[fm][f8][3] + bv.y + r1.y};
        }
    }
}

// ---------------------------------------------------------------------------
// fuse: LN1 per token, gate softmax, fused (fp32), LN2 -> g_hh (split).
// ---------------------------------------------------------------------------
__global__ __launch_bounds__(256)
void fuse_k(const float* __restrict__ s0, const float* __restrict__ s1,
            const float* __restrict__ s2,
            const float* __restrict__ ln1g, const float* __restrict__ ln1b,
            const float* __restrict__ gw,   const float* __restrict__ gb,
            const float* __restrict__ ln2g, const float* __restrict__ ln2b,
            float* __restrict__ out_fused, int B)
{
    __shared__ float s_gw[2304];
    __shared__ float s_ln[1024];
    for (int i = threadIdx.x; i < 2304; i += 256) s_gw[i] = gw[i];
    if (threadIdx.x < 256) {
        int i = threadIdx.x;
        s_ln[i]       = ln1g[i];
        s_ln[256 + i] = ln1b[i];
        s_ln[512 + i] = ln2g[i];
        s_ln[768 + i] = ln2b[i];
    }
    __syncthreads();

    int warp = threadIdx.x >> 5, lane = threadIdx.x & 31;
    int d0 = lane * 8;
    const float* srcs[3] = {s0, s1, s2};

    for (int b = blockIdx.x * 8 + warp; b < B; b += gridDim.x * 8) {
        float y[3][8];
        float gpart[3] = {0.f, 0.f, 0.f};
        #pragma unroll
        for (int t = 0; t < 3; t++) {
            float x[8];
            const float* row = g_x + ((size_t)b * 3 + t) * 256;
            *(float4*)&x[0] = *(const float4*)(row + d0);
            *(float4*)&x[4] = *(const float4*)(row + d0 + 4);
            float s = 0.f;
            #pragma unroll
            for (int j = 0; j < 8; j++) s += x[j];
            s = wsum(s);
            float mu = s * (1.f / 256.f);
            float vv = 0.f;
            #pragma unroll
            for (int j = 0; j < 8; j++) { float d = x[j] - mu; vv += d * d; }
            vv = wsum(vv);
            float rs = rsqrtf(vv * (1.f / 256.f) + 1e-5f);
            #pragma unroll
            for (int j = 0; j < 8; j++)
                y[t][j] = (x[j] - mu) * rs * s_ln[d0 + j] + s_ln[256 + d0 + j];

            float iv[8];
            const float* in = srcs[t] + (size_t)b * 256;
            *(float4*)&iv[0] = *(const float4*)(in + d0);
            *(float4*)&iv[4] = *(const float4*)(in + d0 + 4);
            #pragma unroll
            for (int g = 0; g < 3; g++) {
                const float* wrow = s_gw + g * 768 + t * 256 + d0;
                #pragma unroll
                for (int j = 0; j < 8; j++) gpart[g] += iv[j] * wrow[j];
            }
        }
        float gl[3];
        #pragma unroll
        for (int g = 0; g < 3; g++) gl[g] = wsum(gpart[g]) + gb[g];
        float mx = fmaxf(gl[0], fmaxf(gl[1], gl[2]));
        float e0 = expf(gl[0] - mx), e1 = expf(gl[1] - mx), e2 = expf(gl[2] - mx);
        float inv = 1.f / (e0 + e1 + e2);
        float w0 = e0 * inv, w1 = e1 * inv, w2 = e2 * inv;

        float f[8];
        #pragma unroll
        for (int j = 0; j < 8; j++)
            f[j] = w0 * y[0][j] + w1 * y[1][j] + w2 * y[2][j];
        if (out_fused) {
            float* orow = out_fused + (size_t)b * 256 + d0;
            *(float4*)orow       = *(float4*)&f[0];
            *(float4*)(orow + 4) = *(float4*)&f[4];
        }
        float s2v = 0.f;
        #pragma unroll
        for (int j = 0; j < 8; j++) s2v += f[j];
        s2v = wsum(s2v);
        float mu2 = s2v * (1.f / 256.f);
        float vv2 = 0.f;
        #pragma unroll
        for (int j = 0; j < 8; j++) { float d = f[j] - mu2; vv2 += d * d; }
        vv2 = wsum(vv2);
        float rs2 = rsqrtf(vv2 * (1.f / 256.f) + 1e-5f);
        u32 hi[4], lo[4];
        #pragma unroll
        for (int j = 0; j < 8; j += 2) {
            float h0 = (f[j]   - mu2) * rs2 * s_ln[512 + d0 + j]   + s_ln[768 + d0 + j];
            float h1 = (f[j+1] - mu2) * rs2 * s_ln[512 + d0 + j+1] + s_ln[768 + d0 + j+1];
            split2(h0, h1, hi[j >> 1], lo[j >> 1]);
        }
        __nv_bfloat16* hrow = g_hh + (size_t)b * 512 + d0;
        *(uint4*)hrow         = *(uint4*)hi;
        *(uint4*)(hrow + 256) = *(uint4*)lo;
    }
}

// ---------------------------------------------------------------------------
// deephead: hh -> (w1,GELU) -> h2(smem split) -> (w2,GELU) -> h3(smem) -> logits
// smem: A 8x16K (128K) | W 2x16K (32K) | H2A 4x16K (64K) = 224K, occ 1
// ---------------------------------------------------------------------------
__global__ __launch_bounds__(256)
void deephead(const float* __restrict__ b1, const float* __restrict__ b2,
              const float* __restrict__ w3p, const float* __restrict__ b3p,
              float* __restrict__ outp)
{
    extern __shared__ char dsm[];
    char* dbase = (char*)((((uintptr_t)dsm) + 1023) & ~(uintptr_t)1023);
    u32 base = smem_u32(dbase);
    const u32 wbase = base + 131072;
    const u32 hbase = base + 163840;

    const int tid = threadIdx.x;
    const int lane = tid & 31;
    const int wid = tid >> 5;
    const int warp_m = wid & 3;
    const int warp_n = wid >> 2;
    const int m0 = blockIdx.x * 128;

    const char* Ab  = (const char*)g_hh + (size_t)m0 * 1024;
    const char* W1b = (const char*)(g_w + WOFF_W1);
    const char* W2b = (const char*)(g_w + WOFF_W2);

    const int a_idx12[12] = {0,1,2,3, 0,1,2,3, 4,5,6,7};
    const int w_idx12[12] = {0,1,2,3, 4,5,6,7, 0,1,2,3};

    const int a_mi = lane >> 3;
    const int a_row_base = ((a_mi & 1) << 3) + (lane & 7);
    const int a_kb_sel = (lane >> 4) << 4;
    const int b_row_base = ((a_mi >> 1) << 3) + (lane & 7);
    const int b_kb_sel = ((lane >> 3) & 1) << 4;
    const int quad = lane >> 2, tq = lane & 3;

    // resident A (hh split)
    #pragma unroll
    for (int c = 0; c < 8; c++)
        load_tile<128, 1024>(base + c * 16384, Ab + c * 128);
    asm volatile("cp.async.commit_group;");

    // ---------------- phase 1: h2 = GELU(hh @ w1^T + b1), 2 n-tiles ---------
    #pragma unroll 1
    for (int nt = 0; nt < 2; nt++) {
        const char* Wb = W1b + (size_t)nt * 131072;
        load_tile<128, 1024>(wbase, Wb);          // chunk w_idx12[0]=0
        asm volatile("cp.async.commit_group;");

        float acc[2][8][4];
        #pragma unroll
        for (int i = 0; i < 2; i++)
            #pragma unroll
            for (int j = 0; j < 8; j++)
                #pragma unroll
                for (int q = 0; q < 4; q++) acc[i][j][q] = 0.f;

        #pragma unroll 1
        for (int kc = 0; kc < 12; kc++) {
            if (kc + 1 < 12) {
                load_tile<128, 1024>(wbase + ((kc + 1) & 1) * 16384,
                                     Wb + w_idx12[kc + 1] * 128);
                asm volatile("cp.async.commit_group;");
                asm volatile("cp.async.wait_group 1;");
            } else {
                asm volatile("cp.async.wait_group 0;");
            }
            __syncthreads();

            const u32 As = base + a_idx12[kc] * 16384;
            const u32 Bs = wbase + (kc & 1) * 16384;
            #pragma unroll
            for (int ks = 0; ks < 4; ks++) {
                u32 a[2][4];
                #pragma unroll
                for (int fm = 0; fm < 2; fm++) {
                    int row = warp_m * 32 + fm * 16 + a_row_base;
                    u32 kb = (u32)(ks * 32 + a_kb_sel);
                    u32 ad = As + row * 128 + (kb ^ ((row & 7) << 4));
                    ldsm4(ad, a[fm][0], a[fm][1], a[fm][2], a[fm][3]);
                }
                u32 b[4][4];
                #pragma unroll
                for (int fn = 0; fn < 4; fn++) {
                    int row = warp_n * 64 + fn * 16 + b_row_base;
                    u32 kb = (u32)(ks * 32 + b_kb_sel);
                    u32 bd = Bs + row * 128 + (kb ^ ((row & 7) << 4));
                    ldsm4(bd, b[fn][0], b[fn][1], b[fn][2], b[fn][3]);
                }
                #pragma unroll
                for (int fm = 0; fm < 2; fm++)
                    #pragma unroll
                    for (int f8 = 0; f8 < 8; f8++)
                        mma16816(acc[fm][f8], a[fm],
                                 b[f8 >> 1][(f8 & 1) * 2], b[f8 >> 1][(f8 & 1) * 2 + 1]);
            }
            __syncthreads();
        }

        // h2 epilogue: GELU + split -> smem chunks (swizzled A-operand layout)
        const u32 region = (nt == 0) ? hbase : base;
        #pragma unroll
        for (int fm = 0; fm < 2; fm++) {
            #pragma unroll
            for (int f8 = 0; f8 < 8; f8++) {
                const int nl = warp_n * 64 + f8 * 8 + 2 * tq;   // 0..127 in tile
                const int ncol = nt * 128 + nl;
                float2 bv = *(const float2*)&b1[ncol];
                float v0 = geluf(acc[fm][f8][0] + bv.x);
                float v1 = geluf(acc[fm][f8][1] + bv.y);
                float v2 = geluf(acc[fm][f8][2] + bv.x);
                float v3 = geluf(acc[fm][f8][3] + bv.y);
                u32 h0, l0, h1, l1;
                split2(v0, v1, h0, l0);
                split2(v2, v3, h1, l1);
                const int chl = (ncol >> 6) & 1;
                const u32 hi_slot = region + chl * 16384;
                const u32 lo_slot = region + 32768 + chl * 16384;
                const int bb = (ncol & 63) * 2;                 // byte col < 128
                const int r0 = warp_m * 32 + fm * 16 + quad;
                #pragma unroll
                for (int wh = 0; wh < 2; wh++) {
                    int row = r0 + wh * 8;
                    u32 off = (u32)(row * 128 + (bb & ~15));
                    off ^= (off >> 3) & 0x70;
                    off += (u32)(bb & 15);
                    u32 hv = wh ? h1 : h0;
                    u32 lv = wh ? l1 : l0;
                    asm volatile("st.shared.b32 [%0], %1;" :: "r"(hi_slot + off), "r"(hv));
                    asm volatile("st.shared.b32 [%0], %1;" :: "r"(lo_slot + off), "r"(lv));
                }
            }
        }
        __syncthreads();
    }

    // ---------------- phase 2: h3 = GELU(h2 @ w2^T + b2) --------------------
    const u32 h2slot[8] = {hbase, hbase + 16384, base, base + 16384,
                           hbase + 32768, hbase + 49152, base + 32768, base + 49152};

    load_tile<128, 1024>(wbase, W2b);
    asm volatile("cp.async.commit_group;");

    float acc[2][8][4];
    #pragma unroll
    for (int i = 0; i < 2; i++)
        #pragma unroll
        for (int j = 0; j < 8; j++)
            #pragma unroll
            for (int q = 0; q < 4; q++) acc[i][j][q] = 0.f;

    #pragma unroll 1
    for (int kc = 0; kc < 12; kc++) {
        if (kc + 1 < 12) {
            load_tile<128, 1024>(wbase + ((kc + 1) & 1) * 16384,
                                 W2b + w_idx12[kc + 1] * 128);
            asm volatile("cp.async.commit_group;");
            asm volatile("cp.async.wait_group 1;");
        } else {
            asm volatile("cp.async.wait_group 0;");
        }
        __syncthreads();

        const u32 As = h2slot[a_idx12[kc]];
        const u32 Bs = wbase + (kc & 1) * 16384;
        #pragma unroll
        for (int ks = 0; ks < 4; ks++) {
            u32 a[2][4];
            #pragma unroll
            for (int fm = 0; fm < 2; fm++) {
                int row = warp_m * 32 + fm * 16 + a_row_base;
                u32 kb = (u32)(ks * 32 + a_kb_sel);
                u32 ad = As + row * 128 + (kb ^ ((row & 7) << 4));
                ldsm4(ad, a[fm][0], a[fm][1], a[fm][2], a[fm][3]);
            }
            u32 b[4][4];
            #pragma unroll
            for (int fn = 0; fn < 4; fn++) {
                int row = warp_n * 64 + fn * 16 + b_row_base;
                u32 kb = (u32)(ks * 32 + b_kb_sel);
                u32 bd = Bs + row * 128 + (kb ^ ((row & 7) << 4));
                ldsm4(bd, b[fn][0], b[fn][1], b[fn][2], b[fn][3]);
            }
            #pragma unroll
            for (int fm = 0; fm < 2; fm++)
                #pragma unroll
                for (int f8 = 0; f8 < 8; f8++)
                    mma16816(acc[fm][f8], a[fm],
                             b[f8 >> 1][(f8 & 1) * 2], b[f8 >> 1][(f8 & 1) * 2 + 1]);
        }
        __syncthreads();
    }

    // h3 -> smem fp32 [128][128] at A region (dead now)
    float* h3_s = (float*)dbase;
    #pragma unroll
    for (int fm = 0; fm < 2; fm++) {
        #pragma unroll
        for (int f8 = 0; f8 < 8; f8++) {
            const int n = warp_n * 64 + f8 * 8 + 2 * tq;
            float2 bv = *(const float2*)&b2[n];
            int rl = warp_m * 32 + fm * 16 + quad;
            *(float2*)&h3_s[rl * 128 + n] =
                {geluf(acc[fm][f8][0] + bv.x), geluf(acc[fm][f8][1] + bv.y)};
            *(float2*)&h3_s[(rl + 8) * 128 + n] =
                {geluf(acc[fm][f8][2] + bv.x), geluf(acc[fm][f8][3] + bv.y)};
        }
    }
    __syncthreads();

    // logits
    const int d0 = lane * 4;
    float4 wv[7];
    #pragma unroll
    for (int j = 0; j < 7; j++) wv[j] = *(const float4*)&w3p[j * 128 + d0];
    #pragma unroll 1
    for (int rr = 0; rr < 16; rr++) {
        int row = wid * 16 + rr;
        float4 h = *(const float4*)&h3_s[row * 128 + d0];
        float r[7];
        #pragma unroll
        for (int j = 0; j < 7; j++) {
            float p = h.x * wv[j].x + h.y * wv[j].y + h.z * wv[j].z + h.w * wv[j].w;
            r[j] = wsum(p);
        }
        if (lane == 0) {
            #pragma unroll
            for (int j = 0; j < 7; j++)
                outp[(size_t)(m0 + row) * 7 + j] = r[j] + b3p[j];
        }
    }
}

// ---------------------------------------------------------------------------
extern "C" void kernel_launch(void* const* d_in, const int* in_sizes, int n_in,
                              void* d_out, int out_size)
{
    const float* f_swin    = (const float*)d_in[0];
    const float* f_maxvit  = (const float*)d_in[1];
    const float* f_focal   = (const float*)d_in[2];
    const float* in_proj_w = (const float*)d_in[3];
    const float* in_proj_b = (const float*)d_in[4];
    const float* out_w  = (const float*)d_in[5];
    const float* out_b  = (const float*)d_in[6];
    const float* ln1_g  = (const float*)d_in[7];
    const float* ln1_b  = (const float*)d_in[8];
    const float* gate_w = (const float*)d_in[9];
    const float* gate_b = (const float*)d_in[10];
    const float* ln2_g  = (const float*)d_in[11];
    const float* ln2_b  = (const float*)d_in[12];
    const float* w1 = (const float*)d_in[13];
    const float* b1 = (const float*)d_in[14];
    const float* w2 = (const float*)d_in[15];
    const float* b2 = (const float*)d_in[16];
    const float* w3 = (const float*)d_in[17];
    const float* b3 = (const float*)d_in[18];

    int B = in_sizes[0] / 256;
    if (B > BMAX) B = BMAX;
    int rows3 = 3 * B;

    float* outp = (float*)d_out;
    float* out_logits = outp;
    float* out_fused = (out_size >= B * 263) ? (outp + (size_t)B * 7) : nullptr;

    const int SMEM_QA = 49152 + 32768 + 147456 + 1024;   // 230400
    const int SMEM_OUT = 4 * 16384 + 2 * 16384 + 1024;   // 99328
    const int SMEM_DH = 131072 + 32768 + 65536 + 1024;   // 230400
    cudaFuncSetAttribute(qkv_attn, cudaFuncAttributeMaxDynamicSharedMemorySize, SMEM_QA);
    cudaFuncSetAttribute(gemm_out, cudaFuncAttributeMaxDynamicSharedMemorySize, SMEM_OUT);
    cudaFuncSetAttribute(deephead, cudaFuncAttributeMaxDynamicSharedMemorySize, SMEM_DH);

    dim3 blk(256);

    conv_w_all<<<352, blk>>>(in_proj_w, out_w, w1, w2);
    // fused qkv + attention
    qkv_attn<<<rows3 / 96, blk, SMEM_QA>>>(in_proj_b, f_swin, f_maxvit, f_focal);
    // out-proj + residual
    gemm_out<<<dim3(2, rows3 / 128), blk, SMEM_OUT>>>(out_b, f_swin, f_maxvit, f_focal);
    // LN1 + gate + fused + LN2
    fuse_k<<<1024, blk>>>(f_swin, f_maxvit, f_focal,
                          ln1_g, ln1_b, gate_w, gate_b, ln2_g, ln2_b,
                          out_fused, B);
    // deep head fused
    deephead<<<B / 128, blk, SMEM_DH>>>(b1, b2, w3, b3, out_logits);
}

// round 9
// speedup vs baseline: 1.3890x; 1.0691x over previous
#include <cuda_runtime.h>
#include <cuda_bf16.h>
#include <math.h>
#include <stdint.h>

typedef unsigned int u32;
typedef unsigned long long u64;

#define BMAX 65536

// ---------------------------------------------------------------------------
// Device scratch.
//  g_att : attention out (pre-residual) bf16 [3B, 256]
//  g_hh  : LN2(fused) split bf16             [B, 512]  (hi | lo)
//  g_w   : split weights                     [rows, 512]
// ---------------------------------------------------------------------------
__device__ __nv_bfloat16 g_att[(size_t)BMAX * 3 * 256];
__device__ __nv_bfloat16 g_hh [(size_t)BMAX * 512];
__device__ __nv_bfloat16 g_w  [(size_t)(768 + 256 + 256 + 128) * 512];

#define WOFF_QKV 0
#define WOFF_OUT (768 * 512)
#define WOFF_W1  ((768 + 256) * 512)
#define WOFF_W2  ((768 + 512) * 512)

__device__ __forceinline__ u32 smem_u32(const void* p) {
    u32 a;
    asm("{ .reg .u64 t; cvta.to.shared.u64 t, %1; cvt.u32.u64 %0, t; }" : "=r"(a) : "l"(p));
    return a;
}
__device__ __forceinline__ float geluf(float x) {
    return 0.5f * x * (1.0f + erff(x * 0.7071067811865476f));
}
__device__ __forceinline__ float wsum(float v) {
    #pragma unroll
    for (int o = 16; o > 0; o >>= 1) v += __shfl_xor_sync(0xffffffffu, v, o);
    return v;
}
__device__ __forceinline__ u32 bf2bits(__nv_bfloat162 h) {
    return *reinterpret_cast<u32*>(&h);
}
__device__ __forceinline__ void split2(float a, float b, u32& h, u32& l) {
    __nv_bfloat162 hh = __floats2bfloat162_rn(a, b);
    float ra = a - __bfloat162float(hh.x);
    float rb = b - __bfloat162float(hh.y);
    __nv_bfloat162 ll = __floats2bfloat162_rn(ra, rb);
    h = bf2bits(hh);
    l = bf2bits(ll);
}

// ---------------------------------------------------------------------------
// merged weight conversion: fp32 [rows,256] -> split bf16 [rows,512]
// ---------------------------------------------------------------------------
__global__ __launch_bounds__(256)
void conv_w_all(const float* __restrict__ ipw, const float* __restrict__ ow,
                const float* __restrict__ w1, const float* __restrict__ w2)
{
    int id = blockIdx.x * 256 + threadIdx.x;
    int row = id >> 6;
    int k = (id & 63) << 2;
    const float* src; int r, woff;
    if (row < 768)       { src = ipw; r = row;        woff = WOFF_QKV; }
    else if (row < 1024) { src = ow;  r = row - 768;  woff = WOFF_OUT; }
    else if (row < 1280) { src = w1;  r = row - 1024; woff = WOFF_W1; }
    else                 { src = w2;  r = row - 1280; woff = WOFF_W2; }
    float4 v = *(const float4*)(src + (size_t)r * 256 + k);
    u32 h0, l0, h1, l1;
    split2(v.x, v.y, h0, l0);
    split2(v.z, v.w, h1, l1);
    __nv_bfloat16* dst = g_w + (size_t)woff + (size_t)r * 512;
    u32* hp = (u32*)(dst + k);
    u32* lp = (u32*)(dst + 256 + k);
    hp[0] = h0; hp[1] = h1;
    lp[0] = l0; lp[1] = l1;
}

// ---------------------------------------------------------------------------
// MMA helpers
// ---------------------------------------------------------------------------
__device__ __forceinline__ void ldsm4(u32 addr, u32& r0, u32& r1, u32& r2, u32& r3) {
    asm volatile("ldmatrix.sync.aligned.m8n8.x4.shared.b16 {%0,%1,%2,%3}, [%4];"
                 : "=r"(r0), "=r"(r1), "=r"(r2), "=r"(r3) : "r"(addr));
}
__device__ __forceinline__ void mma16816(float* c, const u32* a, u32 b0, u32 b1) {
    asm volatile(
        "mma.sync.aligned.m16n8k16.row.col.f32.bf16.bf16.f32 "
        "{%0,%1,%2,%3}, {%4,%5,%6,%7}, {%8,%9}, {%0,%1,%2,%3};"
        : "+f"(c[0]), "+f"(c[1]), "+f"(c[2]), "+f"(c[3])
        : "r"(a[0]), "r"(a[1]), "r"(a[2]), "r"(a[3]), "r"(b0), "r"(b1));
}

// load NROWS x 128B chunk into SW128-swizzled smem via cp.async
template<int NROWS, int ROWB>
__device__ __forceinline__ void load_tile(u32 sbase, const char* gb) {
    constexpr int ITERS = NROWS * 8 / 256;
    int tid = threadIdx.x;
    #pragma unroll
    for (int i = 0; i < ITERS; i++) {
        int seg = i * 256 + tid;
        int r = seg >> 3, c = seg & 7;
        u32 off = (u32)(r * 128 + c * 16);
        off ^= (off >> 3) & 0x70;
        asm volatile("cp.async.cg.shared.global [%0], [%1], 16;"
                     :: "r"(sbase + off), "l"(gb + (size_t)r * ROWB + c * 16));
    }
}

// 96-row feature chunk: fp32 -> bf16 direct into swizzled smem
__device__ __forceinline__ void load_Afeat96(u32 sbase, int m0, int c,
                                             const float* __restrict__ s0,
                                             const float* __restrict__ s1,
                                             const float* __restrict__ s2)
{
    int tid = threadIdx.x;
    #pragma unroll
    for (int i = 0; i < 3; i++) {
        int seg = i * 256 + tid;
        int r = seg >> 3, c8 = seg & 7;
        int m = m0 + r;
        int b = m / 3, t = m - 3 * b;
        const float* src = ((t == 0) ? s0 : (t == 1) ? s1 : s2)
                           + (size_t)b * 256 + c * 64 + c8 * 8;
        float4 v0 = *(const float4*)src;
        float4 v1 = *(const float4*)(src + 4);
        u32 w0 = bf2bits(__floats2bfloat162_rn(v0.x, v0.y));
        u32 w1 = bf2bits(__floats2bfloat162_rn(v0.z, v0.w));
        u32 w2 = bf2bits(__floats2bfloat162_rn(v1.x, v1.y));
        u32 w3 = bf2bits(__floats2bfloat162_rn(v1.z, v1.w));
        u32 off = (u32)(r * 128 + c8 * 16);
        off ^= (off >> 3) & 0x70;
        asm volatile("st.shared.v4.b32 [%0], {%1,%2,%3,%4};"
                     :: "r"(sbase + off), "r"(w0), "r"(w1), "r"(w2), "r"(w3));
    }
}

// ---------------------------------------------------------------------------
// qkv_attn_out: fused qkv projection + attention + out-proj.
//  M_TILE = 96 rows = 32 whole batches.
//  1) features -> smem A (48K); qkv GEMM 6 n-tiles -> qkv_s (144K)
//  2) attention from qkv_s; ctx written back into A region (feat dead)
//  3) out-proj: ctx(A) x out_w hi (2 n-tiles x 4 chunks) -> g_att bf16
// smem: A 4x12288 (48K) | W 2x16384 (32K) | qkv 147456 (144K) = 224K
// ---------------------------------------------------------------------------
__global__ __launch_bounds__(256)
void qkv_attn_out(const float* __restrict__ ipb, const float* __restrict__ ob,
                  const float* __restrict__ s0, const float* __restrict__ s1,
                  const float* __restrict__ s2)
{
    extern __shared__ char dsm[];
    char* dbase = (char*)((((uintptr_t)dsm) + 1023) & ~(uintptr_t)1023);
    u32 base = smem_u32(dbase);
    const u32 wbase = base + 49152;
    char* qkv_s = dbase + 81920;              // [96][768] bf16, row stride 1536B

    const int tid = threadIdx.x;
    const int lane = tid & 31;
    const int wid = tid >> 5;
    const int warp_m = wid & 1;               // 0..1 -> 48 rows
    const int warp_n = wid >> 1;              // 0..3 -> 32 cols
    const int m0 = blockIdx.x * 96;

    const char* Wq = (const char*)(g_w + WOFF_QKV);
    const char* Wo = (const char*)(g_w + WOFF_OUT);

    const int a_mi = lane >> 3;
    const int a_row_base = ((a_mi & 1) << 3) + (lane & 7);
    const int a_kb_sel = (lane >> 4) << 4;
    const int b_row_base = ((a_mi >> 1) << 3) + (lane & 7);
    const int b_kb_sel = ((lane >> 3) & 1) << 4;
    const int quad = lane >> 2, tq = lane & 3;

    // ---------------- phase 1: qkv GEMM ----------------
    load_tile<128, 1024>(wbase, Wq);
    asm volatile("cp.async.commit_group;");
    #pragma unroll
    for (int c = 0; c < 4; c++)
        load_Afeat96(base + c * 12288, m0, c, s0, s1, s2);

    #pragma unroll 1
    for (int nt = 0; nt < 6; nt++) {
        float acc[3][4][4];
        #pragma unroll
        for (int i = 0; i < 3; i++)
            #pragma unroll
            for (int j = 0; j < 4; j++)
                #pragma unroll
                for (int q = 0; q < 4; q++) acc[i][j][q] = 0.f;

        #pragma unroll
        for (int kc = 0; kc < 4; kc++) {
            const int gc = nt * 4 + kc;
            if (gc + 1 < 24) {
                const int nnt = (gc + 1) >> 2, nkc = (gc + 1) & 3;
                load_tile<128, 1024>(wbase + ((gc + 1) & 1) * 16384,
                                     Wq + (size_t)nnt * 131072 + nkc * 128);
                asm volatile("cp.async.commit_group;");
                asm volatile("cp.async.wait_group 1;");
            } else {
                asm volatile("cp.async.wait_group 0;");
            }
            __syncthreads();

            const u32 As = base + kc * 12288;
            const u32 Bs = wbase + (gc & 1) * 16384;
            #pragma unroll
            for (int ks = 0; ks < 4; ks++) {
                u32 a[3][4];
                #pragma unroll
                for (int fm = 0; fm < 3; fm++) {
                    int row = warp_m * 48 + fm * 16 + a_row_base;
                    u32 kb = (u32)(ks * 32 + a_kb_sel);
                    u32 ad = As + row * 128 + (kb ^ ((row & 7) << 4));
                    ldsm4(ad, a[fm][0], a[fm][1], a[fm][2], a[fm][3]);
                }
                u32 b[2][4];
                #pragma unroll
                for (int fn = 0; fn < 2; fn++) {
                    int row = warp_n * 32 + fn * 16 + b_row_base;
                    u32 kb = (u32)(ks * 32 + b_kb_sel);
                    u32 bd = Bs + row * 128 + (kb ^ ((row & 7) << 4));
                    ldsm4(bd, b[fn][0], b[fn][1], b[fn][2], b[fn][3]);
                }
                #pragma unroll
                for (int fm = 0; fm < 3; fm++)
                    #pragma unroll
                    for (int f8 = 0; f8 < 4; f8++)
                        mma16816(acc[fm][f8], a[fm],
                                 b[f8 >> 1][(f8 & 1) * 2], b[f8 >> 1][(f8 & 1) * 2 + 1]);
            }
            __syncthreads();
        }

        // park this n-tile's qkv in smem (+bias, bf16)
        #pragma unroll
        for (int fm = 0; fm < 3; fm++) {
            const int r = warp_m * 48 + fm * 16 + quad;
            #pragma unroll
            for (int f8 = 0; f8 < 4; f8++) {
                const int ncol = nt * 128 + warp_n * 32 + f8 * 8 + 2 * tq;
                float2 bv = *(const float2*)&ipb[ncol];
                u32 lo = bf2bits(__floats2bfloat162_rn(acc[fm][f8][0] + bv.x,
                                                       acc[fm][f8][1] + bv.y));
                u32 hi = bf2bits(__floats2bfloat162_rn(acc[fm][f8][2] + bv.x,
                                                       acc[fm][f8][3] + bv.y));
                *(u32*)(qkv_s + (size_t)r * 1536 + ncol * 2)       = lo;
                *(u32*)(qkv_s + (size_t)(r + 8) * 1536 + ncol * 2) = hi;
            }
        }
    }
    __syncthreads();

    // W prologue for out-proj: overlaps attention phase
    load_tile<128, 1024>(wbase, Wo);
    asm volatile("cp.async.commit_group;");

    // ---------------- phase 2: attention; ctx -> A region ----------------
    const int d0 = lane * 8;
    const int ctx_ch = lane >> 3;                 // chunk 0..3 (64-col chunks)
    const int ctx_inb = (d0 & 63) * 2;            // byte offset within chunk row
    #pragma unroll 1
    for (int bl = 0; bl < 4; bl++) {
        int tb = wid * 4 + bl;                 // 0..31 within tile

        float q[3][8], k[3][8], v[3][8];
        #pragma unroll
        for (int t = 0; t < 3; t++) {
            const char* rp = qkv_s + (size_t)(tb * 3 + t) * 1536 + d0 * 2;
            uint4 qr = *(const uint4*)rp;
            uint4 kr = *(const uint4*)(rp + 512);
            uint4 vr = *(const uint4*)(rp + 1024);
            const u32* qw = (const u32*)&qr;
            const u32* kw = (const u32*)&kr;
            const u32* vw = (const u32*)&vr;
            #pragma unroll
            for (int j = 0; j < 4; j++) {
                float2 qf = __bfloat1622float2(*(const __nv_bfloat162*)&qw[j]);
                float2 kf = __bfloat1622float2(*(const __nv_bfloat162*)&kw[j]);
                float2 vf = __bfloat1622float2(*(const __nv_bfloat162*)&vw[j]);
                q[t][2*j] = qf.x; q[t][2*j+1] = qf.y;
                k[t][2*j] = kf.x; k[t][2*j+1] = kf.y;
                v[t][2*j] = vf.x; v[t][2*j+1] = vf.y;
            }
        }
        float s[3][3];
        #pragma unroll
        for (int t = 0; t < 3; t++)
            #pragma unroll
            for (int u = 0; u < 3; u++) {
                float p = 0.f;
                #pragma unroll
                for (int j = 0; j < 8; j++) p += q[t][j] * k[u][j];
                p += __shfl_xor_sync(0xffffffffu, p, 1);
                p += __shfl_xor_sync(0xffffffffu, p, 2);
                p += __shfl_xor_sync(0xffffffffu, p, 4);
                s[t][u] = p * 0.125f;
            }
        #pragma unroll
        for (int t = 0; t < 3; t++) {
            float mx = fmaxf(s[t][0], fmaxf(s[t][1], s[t][2]));
            float e0 = expf(s[t][0] - mx);
            float e1 = expf(s[t][1] - mx);
            float e2 = expf(s[t][2] - mx);
            float inv = 1.f / (e0 + e1 + e2);
            u32 cw[4];
            #pragma unroll
            for (int j = 0; j < 8; j += 2) {
                float c0 = (e0 * v[0][j]   + e1 * v[1][j]   + e2 * v[2][j])   * inv;
                float c1 = (e0 * v[0][j+1] + e1 * v[1][j+1] + e2 * v[2][j+1]) * inv;
                cw[j >> 1] = bf2bits(__floats2bfloat162_rn(c0, c1));
            }
            // write ctx into A region, GEMM-operand (swizzled chunk) layout
            int row = tb * 3 + t;
            u32 off = (u32)(row * 128 + ctx_inb);
            off ^= (off >> 3) & 0x70;
            asm volatile("st.shared.v4.b32 [%0], {%1,%2,%3,%4};"
                         :: "r"(base + ctx_ch * 12288 + off),
                            "r"(cw[0]), "r"(cw[1]), "r"(cw[2]), "r"(cw[3]));
        }
    }
    __syncthreads();

    // ---------------- phase 3: out-proj (ctx x out_w hi) -> g_att bf16 -----
    #pragma unroll 1
    for (int nt2 = 0; nt2 < 2; nt2++) {
        float acc[3][4][4];
        #pragma unroll
        for (int i = 0; i < 3; i++)
            #pragma unroll
            for (int j = 0; j < 4; j++)
                #pragma unroll
                for (int q = 0; q < 4; q++) acc[i][j][q] = 0.f;

        #pragma unroll
        for (int kc = 0; kc < 4; kc++) {
            const int gc = nt2 * 4 + kc;
            if (gc + 1 < 8) {
                load_tile<128, 1024>(wbase + ((gc + 1) & 1) * 16384,
                                     Wo + (size_t)((gc + 1) >> 2) * 131072 + ((gc + 1) & 3) * 128);
                asm volatile("cp.async.commit_group;");
                asm volatile("cp.async.wait_group 1;");
            } else {
                asm volatile("cp.async.wait_group 0;");
            }
            __syncthreads();

            const u32 As = base + kc * 12288;
            const u32 Bs = wbase + (gc & 1) * 16384;
            #pragma unroll
            for (int ks = 0; ks < 4; ks++) {
                u32 a[3][4];
                #pragma unroll
                for (int fm = 0; fm < 3; fm++) {
                    int row = warp_m * 48 + fm * 16 + a_row_base;
                    u32 kb = (u32)(ks * 32 + a_kb_sel);
                    u32 ad = As + row * 128 + (kb ^ ((row & 7) << 4));
                    ldsm4(ad, a[fm][0], a[fm][1], a[fm][2], a[fm][3]);
                }
                u32 b[2][4];
                #pragma unroll
                for (int fn = 0; fn < 2; fn++) {
                    int row = warp_n * 32 + fn * 16 + b_row_base;
                    u32 kb = (u32)(ks * 32 + b_kb_sel);
                    u32 bd = Bs + row * 128 + (kb ^ ((row & 7) << 4));
                    ldsm4(bd, b[fn][0], b[fn][1], b[fn][2], b[fn][3]);
                }
                #pragma unroll
                for (int fm = 0; fm < 3; fm++)
                    #pragma unroll
                    for (int f8 = 0; f8 < 4; f8++)
                        mma16816(acc[fm][f8], a[fm],
                                 b[f8 >> 1][(f8 & 1) * 2], b[f8 >> 1][(f8 & 1) * 2 + 1]);
            }
            __syncthreads();
        }

        // epilogue: +out_b, bf16, store att
        #pragma unroll
        for (int fm = 0; fm < 3; fm++) {
            const int r = warp_m * 48 + fm * 16 + quad;
            #pragma unroll
            for (int f8 = 0; f8 < 4; f8++) {
                const int ncol = nt2 * 128 + warp_n * 32 + f8 * 8 + 2 * tq;
                float2 bv = *(const float2*)&ob[ncol];
                u32 lo = bf2bits(__floats2bfloat162_rn(acc[fm][f8][0] + bv.x,
                                                       acc[fm][f8][1] + bv.y));
                u32 hi = bf2bits(__floats2bfloat162_rn(acc[fm][f8][2] + bv.x,
                                                       acc[fm][f8][3] + bv.y));
                *(u32*)&g_att[(size_t)(m0 + r) * 256 + ncol]     = lo;
                *(u32*)&g_att[(size_t)(m0 + r + 8) * 256 + ncol] = hi;
            }
        }
    }
}

// ---------------------------------------------------------------------------
// fuse: x = att(bf16) + feat; LN1, gate softmax, fused (fp32), LN2 -> g_hh.
// ---------------------------------------------------------------------------
__global__ __launch_bounds__(256)
void fuse_k(const float* __restrict__ s0, const float* __restrict__ s1,
            const float* __restrict__ s2,
            const float* __restrict__ ln1g, const float* __restrict__ ln1b,
            const float* __restrict__ gw,   const float* __restrict__ gb,
            const float* __restrict__ ln2g, const float* __restrict__ ln2b,
            float* __restrict__ out_fused, int B)
{
    __shared__ float s_gw[2304];
    __shared__ float s_ln[1024];
    for (int i = threadIdx.x; i < 2304; i += 256) s_gw[i] = gw[i];
    if (threadIdx.x < 256) {
        int i = threadIdx.x;
        s_ln[i]       = ln1g[i];
        s_ln[256 + i] = ln1b[i];
        s_ln[512 + i] = ln2g[i];
        s_ln[768 + i] = ln2b[i];
    }
    __syncthreads();

    int warp = threadIdx.x >> 5, lane = threadIdx.x & 31;
    int d0 = lane * 8;
    const float* srcs[3] = {s0, s1, s2};

    for (int b = blockIdx.x * 8 + warp; b < B; b += gridDim.x * 8) {
        float y[3][8];
        float gpart[3] = {0.f, 0.f, 0.f};
        #pragma unroll
        for (int t = 0; t < 3; t++) {
            // features (residual + gate input)
            float iv[8];
            const float* in = srcs[t] + (size_t)b * 256;
            *(float4*)&iv[0] = *(const float4*)(in + d0);
            *(float4*)&iv[4] = *(const float4*)(in + d0 + 4);
            // att (bf16) -> x = att + feat
            float x[8];
            uint4 ar = *(const uint4*)(g_att + ((size_t)b * 3 + t) * 256 + d0);
            const u32* aw = (const u32*)&ar;
            #pragma unroll
            for (int j = 0; j < 4; j++) {
                float2 af = __bfloat1622float2(*(const __nv_bfloat162*)&aw[j]);
                x[2*j]   = af.x + iv[2*j];
                x[2*j+1] = af.y + iv[2*j+1];
            }
            float s = 0.f;
            #pragma unroll
            for (int j = 0; j < 8; j++) s += x[j];
            s = wsum(s);
            float mu = s * (1.f / 256.f);
            float vv = 0.f;
            #pragma unroll
            for (int j = 0; j < 8; j++) { float d = x[j] - mu; vv += d * d; }
            vv = wsum(vv);
            float rs = rsqrtf(vv * (1.f / 256.f) + 1e-5f);
            #pragma unroll
            for (int j = 0; j < 8; j++)
                y[t][j] = (x[j] - mu) * rs * s_ln[d0 + j] + s_ln[256 + d0 + j];

            #pragma unroll
            for (int g = 0; g < 3; g++) {
                const float* wrow = s_gw + g * 768 + t * 256 + d0;
                #pragma unroll
                for (int j = 0; j < 8; j++) gpart[g] += iv[j] * wrow[j];
            }
        }
        float gl[3];
        #pragma unroll
        for (int g = 0; g < 3; g++) gl[g] = wsum(gpart[g]) + gb[g];
        float mx = fmaxf(gl[0], fmaxf(gl[1], gl[2]));
        float e0 = expf(gl[0] - mx), e1 = expf(gl[1] - mx), e2 = expf(gl[2] - mx);
        float inv = 1.f / (e0 + e1 + e2);
        float w0 = e0 * inv, w1 = e1 * inv, w2 = e2 * inv;

        float f[8];
        #pragma unroll
        for (int j = 0; j < 8; j++)
            f[j] = w0 * y[0][j] + w1 * y[1][j] + w2 * y[2][j];
        if (out_fused) {
            float* orow = out_fused + (size_t)b * 256 + d0;
            *(float4*)orow       = *(float4*)&f[0];
            *(float4*)(orow + 4) = *(float4*)&f[4];
        }
        float s2v = 0.f;
        #pragma unroll
        for (int j = 0; j < 8; j++) s2v += f[j];
        s2v = wsum(s2v);
        float mu2 = s2v * (1.f / 256.f);
        float vv2 = 0.f;
        #pragma unroll
        for (int j = 0; j < 8; j++) { float d = f[j] - mu2; vv2 += d * d; }
        vv2 = wsum(vv2);
        float rs2 = rsqrtf(vv2 * (1.f / 256.f) + 1e-5f);
        u32 hi[4], lo[4];
        #pragma unroll
        for (int j = 0; j < 8; j += 2) {
            float h0 = (f[j]   - mu2) * rs2 * s_ln[512 + d0 + j]   + s_ln[768 + d0 + j];
            float h1 = (f[j+1] - mu2) * rs2 * s_ln[512 + d0 + j+1] + s_ln[768 + d0 + j+1];
            split2(h0, h1, hi[j >> 1], lo[j >> 1]);
        }
        __nv_bfloat16* hrow = g_hh + (size_t)b * 512 + d0;
        *(uint4*)hrow         = *(uint4*)hi;
        *(uint4*)(hrow + 256) = *(uint4*)lo;
    }
}

// ---------------------------------------------------------------------------
// deephead: hh -> (w1,GELU) -> h2(smem split) -> (w2,GELU) -> h3(smem) -> logits
// ---------------------------------------------------------------------------
__global__ __launch_bounds__(256)
void deephead(const float* __restrict__ b1, const float* __restrict__ b2,
              const float* __restrict__ w3p, const float* __restrict__ b3p,
              float* __restrict__ outp)
{
    extern __shared__ char dsm[];
    char* dbase = (char*)((((uintptr_t)dsm) + 1023) & ~(uintptr_t)1023);
    u32 base = smem_u32(dbase);
    const u32 wbase = base + 131072;
    const u32 hbase = base + 163840;

    const int tid = threadIdx.x;
    const int lane = tid & 31;
    const int wid = tid >> 5;
    const int warp_m = wid & 3;
    const int warp_n = wid >> 2;
    const int m0 = blockIdx.x * 128;

    const char* Ab  = (const char*)g_hh + (size_t)m0 * 1024;
    const char* W1b = (const char*)(g_w + WOFF_W1);
    const char* W2b = (const char*)(g_w + WOFF_W2);

    const int a_idx12[12] = {0,1,2,3, 0,1,2,3, 4,5,6,7};
    const int w_idx12[12] = {0,1,2,3, 4,5,6,7, 0,1,2,3};

    const int a_mi = lane >> 3;
    const int a_row_base = ((a_mi & 1) << 3) + (lane & 7);
    const int a_kb_sel = (lane >> 4) << 4;
    const int b_row_base = ((a_mi >> 1) << 3) + (lane & 7);
    const int b_kb_sel = ((lane >> 3) & 1) << 4;
    const int quad = lane >> 2, tq = lane & 3;

    #pragma unroll
    for (int c = 0; c < 8; c++)
        load_tile<128, 1024>(base + c * 16384, Ab + c * 128);
    asm volatile("cp.async.commit_group;");

    // ---------------- phase 1: h2 = GELU(hh @ w1^T + b1), 2 n-tiles ---------
    #pragma unroll 1
    for (int nt = 0; nt < 2; nt++) {
        const char* Wb = W1b + (size_t)nt * 131072;
        load_tile<128, 1024>(wbase, Wb);
        asm volatile("cp.async.commit_group;");

        float acc[2][8][4];
        #pragma unroll
        for (int i = 0; i < 2; i++)
            #pragma unroll
            for (int j = 0; j < 8; j++)
                #pragma unroll
                for (int q = 0; q < 4; q++) acc[i][j][q] = 0.f;

        #pragma unroll 1
        for (int kc = 0; kc < 12; kc++) {
            if (kc + 1 < 12) {
                load_tile<128, 1024>(wbase + ((kc + 1) & 1) * 16384,
                                     Wb + w_idx12[kc + 1] * 128);
                asm volatile("cp.async.commit_group;");
                asm volatile("cp.async.wait_group 1;");
            } else {
                asm volatile("cp.async.wait_group 0;");
            }
            __syncthreads();

            const u32 As = base + a_idx12[kc] * 16384;
            const u32 Bs = wbase + (kc & 1) * 16384;
            #pragma unroll
            for (int ks = 0; ks < 4; ks++) {
                u32 a[2][4];
                #pragma unroll
                for (int fm = 0; fm < 2; fm++) {
                    int row = warp_m * 32 + fm * 16 + a_row_base;
                    u32 kb = (u32)(ks * 32 + a_kb_sel);
                    u32 ad = As + row * 128 + (kb ^ ((row & 7) << 4));
                    ldsm4(ad, a[fm][0], a[fm][1], a[fm][2], a[fm][3]);
                }
                u32 b[4][4];
                #pragma unroll
                for (int fn = 0; fn < 4; fn++) {
                    int row = warp_n * 64 + fn * 16 + b_row_base;
                    u32 kb = (u32)(ks * 32 + b_kb_sel);
                    u32 bd = Bs + row * 128 + (kb ^ ((row & 7) << 4));
                    ldsm4(bd, b[fn][0], b[fn][1], b[fn][2], b[fn][3]);
                }
                #pragma unroll
                for (int fm = 0; fm < 2; fm++)
                    #pragma unroll
                    for (int f8 = 0; f8 < 8; f8++)
                        mma16816(acc[fm][f8], a[fm],
                                 b[f8 >> 1][(f8 & 1) * 2], b[f8 >> 1][(f8 & 1) * 2 + 1]);
            }
            __syncthreads();
        }

        const u32 region = (nt == 0) ? hbase : base;
        #pragma unroll
        for (int fm = 0; fm < 2; fm++) {
            #pragma unroll
            for (int f8 = 0; f8 < 8; f8++) {
                const int nl = warp_n * 64 + f8 * 8 + 2 * tq;
                const int ncol = nt * 128 + nl;
                float2 bv = *(const float2*)&b1[ncol];
                float v0 = geluf(acc[fm][f8][0] + bv.x);
                float v1 = geluf(acc[fm][f8][1] + bv.y);
                float v2 = geluf(acc[fm][f8][2] + bv.x);
                float v3 = geluf(acc[fm][f8][3] + bv.y);
                u32 h0, l0, h1, l1;
                split2(v0, v1, h0, l0);
                split2(v2, v3, h1, l1);
                const int chl = (ncol >> 6) & 1;
                const u32 hi_slot = region + chl * 16384;
                const u32 lo_slot = region + 32768 + chl * 16384;
                const int bb = (ncol & 63) * 2;
                const int r0 = warp_m * 32 + fm * 16 + quad;
                #pragma unroll
                for (int wh = 0; wh < 2; wh++) {
                    int row = r0 + wh * 8;
                    u32 off = (u32)(row * 128 + (bb & ~15));
                    off ^= (off >> 3) & 0x70;
                    off += (u32)(bb & 15);
                    u32 hv = wh ? h1 : h0;
                    u32 lv = wh ? l1 : l0;
                    asm volatile("st.shared.b32 [%0], %1;" :: "r"(hi_slot + off), "r"(hv));
                    asm volatile("st.shared.b32 [%0], %1;" :: "r"(lo_slot + off), "r"(lv));
                }
            }
        }
        __syncthreads();
    }

    // ---------------- phase 2: h3 = GELU(h2 @ w2^T + b2) --------------------
    const u32 h2slot[8] = {hbase, hbase + 16384, base, base + 16384,
                           hbase + 32768, hbase + 49152, base + 32768, base + 49152};

    load_tile<128, 1024>(wbase, W2b);
    asm volatile("cp.async.commit_group;");

    float acc[2][8][4];
    #pragma unroll
    for (int i = 0; i < 2; i++)
        #pragma unroll
        for (int j = 0; j < 8; j++)
            #pragma unroll
            for (int q = 0; q < 4; q++) acc[i][j][q] = 0.f;

    #pragma unroll 1
    for (int kc = 0; kc < 12; kc++) {
        if (kc + 1 < 12) {
            load_tile<128, 1024>(wbase + ((kc + 1) & 1) * 16384,
                                 W2b + w_idx12[kc + 1] * 128);
            asm volatile("cp.async.commit_group;");
            asm volatile("cp.async.wait_group 1;");
        } else {
            asm volatile("cp.async.wait_group 0;");
        }
        __syncthreads();

        const u32 As = h2slot[a_idx12[kc]];
        const u32 Bs = wbase + (kc & 1) * 16384;
        #pragma unroll
        for (int ks = 0; ks < 4; ks++) {
            u32 a[2][4];
            #pragma unroll
            for (int fm = 0; fm < 2; fm++) {
                int row = warp_m * 32 + fm * 16 + a_row_base;
                u32 kb = (u32)(ks * 32 + a_kb_sel);
                u32 ad = As + row * 128 + (kb ^ ((row & 7) << 4));
                ldsm4(ad, a[fm][0], a[fm][1], a[fm][2], a[fm][3]);
            }
            u32 b[4][4];
            #pragma unroll
            for (int fn = 0; fn < 4; fn++) {
                int row = warp_n * 64 + fn * 16 + b_row_base;
                u32 kb = (u32)(ks * 32 + b_kb_sel);
                u32 bd = Bs + row * 128 + (kb ^ ((row & 7) << 4));
                ldsm4(bd, b[fn][0], b[fn][1], b[fn][2], b[fn][3]);
            }
            #pragma unroll
            for (int fm = 0; fm < 2; fm++)
                #pragma unroll
                for (int f8 = 0; f8 < 8; f8++)
                    mma16816(acc[fm][f8], a[fm],
                             b[f8 >> 1][(f8 & 1) * 2], b[f8 >> 1][(f8 & 1) * 2 + 1]);
        }
        __syncthreads();
    }

    float* h3_s = (float*)dbase;
    #pragma unroll
    for (int fm = 0; fm < 2; fm++) {
        #pragma unroll
        for (int f8 = 0; f8 < 8; f8++) {
            const int n = warp_n * 64 + f8 * 8 + 2 * tq;
            float2 bv = *(const float2*)&b2[n];
            int rl = warp_m * 32 + fm * 16 + quad;
            *(float2*)&h3_s[rl * 128 + n] =
                {geluf(acc[fm][f8][0] + bv.x), geluf(acc[fm][f8][1] + bv.y)};
            *(float2*)&h3_s[(rl + 8) * 128 + n] =
                {geluf(acc[fm][f8][2] + bv.x), geluf(acc[fm][f8][3] + bv.y)};
        }
    }
    __syncthreads();

    const int d0 = lane * 4;
    float4 wv[7];
    #pragma unroll
    for (int j = 0; j < 7; j++) wv[j] = *(const float4*)&w3p[j * 128 + d0];
    #pragma unroll 1
    for (int rr = 0; rr < 16; rr++) {
        int row = wid * 16 + rr;
        float4 h = *(const float4*)&h3_s[row * 128 + d0];
        float r[7];
        #pragma unroll
        for (int j = 0; j < 7; j++) {
            float p = h.x * wv[j].x + h.y * wv[j].y + h.z * wv[j].z + h.w * wv[j].w;
            r[j] = wsum(p);
        }
        if (lane == 0) {
            #pragma unroll
            for (int j = 0; j < 7; j++)
                outp[(size_t)(m0 + row) * 7 + j] = r[j] + b3p[j];
        }
    }
}

// ---------------------------------------------------------------------------
extern "C" void kernel_launch(void* const* d_in, const int* in_sizes, int n_in,
                              void* d_out, int out_size)
{
    const float* f_swin    = (const float*)d_in[0];
    const float* f_maxvit  = (const float*)d_in[1];
    const float* f_focal   = (const float*)d_in[2];
    const float* in_proj_w = (const float*)d_in[3];
    const float* in_proj_b = (const float*)d_in[4];
    const float* out_w  = (const float*)d_in[5];
    const float* out_b  = (const float*)d_in[6];
    const float* ln1_g  = (const float*)d_in[7];
    const float* ln1_b  = (const float*)d_in[8];
    const float* gate_w = (const float*)d_in[9];
    const float* gate_b = (const float*)d_in[10];
    const float* ln2_g  = (const float*)d_in[11];
    const float* ln2_b  = (const float*)d_in[12];
    const float* w1 = (const float*)d_in[13];
    const float* b1 = (const float*)d_in[14];
    const float* w2 = (const float*)d_in[15];
    const float* b2 = (const float*)d_in[16];
    const float* w3 = (const float*)d_in[17];
    const float* b3 = (const float*)d_in[18];

    int B = in_sizes[0] / 256;
    if (B > BMAX) B = BMAX;
    int rows3 = 3 * B;

    float* outp = (float*)d_out;
    float* out_logits = outp;
    float* out_fused = (out_size >= B * 263) ? (outp + (size_t)B * 7) : nullptr;

    const int SMEM_QA = 49152 + 32768 + 147456 + 1024;   // 230400
    const int SMEM_DH = 131072 + 32768 + 65536 + 1024;   // 230400
    cudaFuncSetAttribute(qkv_attn_out, cudaFuncAttributeMaxDynamicSharedMemorySize, SMEM_QA);
    cudaFuncSetAttribute(deephead, cudaFuncAttributeMaxDynamicSharedMemorySize, SMEM_DH);

    dim3 blk(256);

    conv_w_all<<<352, blk>>>(in_proj_w, out_w, w1, w2);
    // fused qkv + attention + out-proj
    qkv_attn_out<<<rows3 / 96, blk, SMEM_QA>>>(in_proj_b, out_b,
                                               f_swin, f_maxvit, f_focal);
    // residual + LN1 + gate + fused + LN2
    fuse_k<<<1024, blk>>>(f_swin, f_maxvit, f_focal,
                          ln1_g, ln1_b, gate_w, gate_b, ln2_g, ln2_b,
                          out_fused, B);
    // deep head fused
    deephead<<<B / 128, blk, SMEM_DH>>>(b1, b2, w3, b3, out_logits);
}

// round 10
// speedup vs baseline: 1.4860x; 1.0699x over previous
#include <cuda_runtime.h>
#include <cuda_bf16.h>
#include <math.h>
#include <stdint.h>

typedef unsigned int u32;
typedef unsigned long long u64;

#define BMAX 65536

// ---------------------------------------------------------------------------
// Device scratch.
//  g_att : attention out (pre-residual) bf16 [3B, 256]
//  g_hh  : LN2(fused) split bf16             [B, 512]  (hi | lo)
//  g_w   : split weights                     [rows, 512]
// ---------------------------------------------------------------------------
__device__ __nv_bfloat16 g_att[(size_t)BMAX * 3 * 256];
__device__ __nv_bfloat16 g_hh [(size_t)BMAX * 512];
__device__ __nv_bfloat16 g_w  [(size_t)(768 + 256 + 256 + 128) * 512];

#define WOFF_QKV 0
#define WOFF_OUT (768 * 512)
#define WOFF_W1  ((768 + 256) * 512)
#define WOFF_W2  ((768 + 512) * 512)

__device__ __forceinline__ u32 smem_u32(const void* p) {
    u32 a;
    asm("{ .reg .u64 t; cvta.to.shared.u64 t, %1; cvt.u32.u64 %0, t; }" : "=r"(a) : "l"(p));
    return a;
}
__device__ __forceinline__ float geluf(float x) {
    return 0.5f * x * (1.0f + erff(x * 0.7071067811865476f));
}
__device__ __forceinline__ float wsum(float v) {
    #pragma unroll
    for (int o = 16; o > 0; o >>= 1) v += __shfl_xor_sync(0xffffffffu, v, o);
    return v;
}
__device__ __forceinline__ u32 bf2bits(__nv_bfloat162 h) {
    return *reinterpret_cast<u32*>(&h);
}
__device__ __forceinline__ void split2(float a, float b, u32& h, u32& l) {
    __nv_bfloat162 hh = __floats2bfloat162_rn(a, b);
    float ra = a - __bfloat162float(hh.x);
    float rb = b - __bfloat162float(hh.y);
    __nv_bfloat162 ll = __floats2bfloat162_rn(ra, rb);
    h = bf2bits(hh);
    l = bf2bits(ll);
}

// ---------------------------------------------------------------------------
// merged weight conversion: fp32 [rows,256] -> split bf16 [rows,512]
// ---------------------------------------------------------------------------
__global__ __launch_bounds__(256)
void conv_w_all(const float* __restrict__ ipw, const float* __restrict__ ow,
                const float* __restrict__ w1, const float* __restrict__ w2)
{
    int id = blockIdx.x * 256 + threadIdx.x;
    int row = id >> 6;
    int k = (id & 63) << 2;
    const float* src; int r, woff;
    if (row < 768)       { src = ipw; r = row;        woff = WOFF_QKV; }
    else if (row < 1024) { src = ow;  r = row - 768;  woff = WOFF_OUT; }
    else if (row < 1280) { src = w1;  r = row - 1024; woff = WOFF_W1; }
    else                 { src = w2;  r = row - 1280; woff = WOFF_W2; }
    float4 v = *(const float4*)(src + (size_t)r * 256 + k);
    u32 h0, l0, h1, l1;
    split2(v.x, v.y, h0, l0);
    split2(v.z, v.w, h1, l1);
    __nv_bfloat16* dst = g_w + (size_t)woff + (size_t)r * 512;
    u32* hp = (u32*)(dst + k);
    u32* lp = (u32*)(dst + 256 + k);
    hp[0] = h0; hp[1] = h1;
    lp[0] = l0; lp[1] = l1;
}

// ---------------------------------------------------------------------------
// MMA helpers
// ---------------------------------------------------------------------------
__device__ __forceinline__ void ldsm4(u32 addr, u32& r0, u32& r1, u32& r2, u32& r3) {
    asm volatile("ldmatrix.sync.aligned.m8n8.x4.shared.b16 {%0,%1,%2,%3}, [%4];"
                 : "=r"(r0), "=r"(r1), "=r"(r2), "=r"(r3) : "r"(addr));
}
__device__ __forceinline__ void mma16816(float* c, const u32* a, u32 b0, u32 b1) {
    asm volatile(
        "mma.sync.aligned.m16n8k16.row.col.f32.bf16.bf16.f32 "
        "{%0,%1,%2,%3}, {%4,%5,%6,%7}, {%8,%9}, {%0,%1,%2,%3};"
        : "+f"(c[0]), "+f"(c[1]), "+f"(c[2]), "+f"(c[3])
        : "r"(a[0]), "r"(a[1]), "r"(a[2]), "r"(a[3]), "r"(b0), "r"(b1));
}

// load NROWS x 128B chunk into SW128-swizzled smem via cp.async
template<int NROWS, int ROWB>
__device__ __forceinline__ void load_tile(u32 sbase, const char* gb) {
    constexpr int ITERS = NROWS * 8 / 256;
    int tid = threadIdx.x;
    #pragma unroll
    for (int i = 0; i < ITERS; i++) {
        int seg = i * 256 + tid;
        int r = seg >> 3, c = seg & 7;
        u32 off = (u32)(r * 128 + c * 16);
        off ^= (off >> 3) & 0x70;
        asm volatile("cp.async.cg.shared.global [%0], [%1], 16;"
                     :: "r"(sbase + off), "l"(gb + (size_t)r * ROWB + c * 16));
    }
}

// 96-row feature chunk: fp32 -> bf16 direct into swizzled smem
__device__ __forceinline__ void load_Afeat96(u32 sbase, int m0, int c,
                                             const float* __restrict__ s0,
                                             const float* __restrict__ s1,
                                             const float* __restrict__ s2)
{
    int tid = threadIdx.x;
    #pragma unroll
    for (int i = 0; i < 3; i++) {
        int seg = i * 256 + tid;
        int r = seg >> 3, c8 = seg & 7;
        int m = m0 + r;
        int b = m / 3, t = m - 3 * b;
        const float* src = ((t == 0) ? s0 : (t == 1) ? s1 : s2)
                           + (size_t)b * 256 + c * 64 + c8 * 8;
        float4 v0 = *(const float4*)src;
        float4 v1 = *(const float4*)(src + 4);
        u32 w0 = bf2bits(__floats2bfloat162_rn(v0.x, v0.y));
        u32 w1 = bf2bits(__floats2bfloat162_rn(v0.z, v0.w));
        u32 w2 = bf2bits(__floats2bfloat162_rn(v1.x, v1.y));
        u32 w3 = bf2bits(__floats2bfloat162_rn(v1.z, v1.w));
        u32 off = (u32)(r * 128 + c8 * 16);
        off ^= (off >> 3) & 0x70;
        asm volatile("st.shared.v4.b32 [%0], {%1,%2,%3,%4};"
                     :: "r"(sbase + off), "r"(w0), "r"(w1), "r"(w2), "r"(w3));
    }
}

// ---------------------------------------------------------------------------
// qkv_attn_out: fused qkv projection + attention + out-proj.
//  M_TILE = 96 rows = 32 whole batches.
// smem: A 4x12288 (48K) | W 2x16384 (32K) | qkv 147456 (144K) = 224K
// ---------------------------------------------------------------------------
__global__ __launch_bounds__(256)
void qkv_attn_out(const float* __restrict__ ipb, const float* __restrict__ ob,
                  const float* __restrict__ s0, const float* __restrict__ s1,
                  const float* __restrict__ s2)
{
    extern __shared__ char dsm[];
    char* dbase = (char*)((((uintptr_t)dsm) + 1023) & ~(uintptr_t)1023);
    u32 base = smem_u32(dbase);
    const u32 wbase = base + 49152;
    char* qkv_s = dbase + 81920;              // [96][768] bf16, row stride 1536B

    const int tid = threadIdx.x;
    const int lane = tid & 31;
    const int wid = tid >> 5;
    const int warp_m = wid & 1;               // 0..1 -> 48 rows
    const int warp_n = wid >> 1;              // 0..3 -> 32 cols
    const int m0 = blockIdx.x * 96;

    const char* Wq = (const char*)(g_w + WOFF_QKV);
    const char* Wo = (const char*)(g_w + WOFF_OUT);

    const int a_mi = lane >> 3;
    const int a_row_base = ((a_mi & 1) << 3) + (lane & 7);
    const int a_kb_sel = (lane >> 4) << 4;
    const int b_row_base = ((a_mi >> 1) << 3) + (lane & 7);
    const int b_kb_sel = ((lane >> 3) & 1) << 4;
    const int quad = lane >> 2, tq = lane & 3;

    // ---------------- phase 1: qkv GEMM ----------------
    load_tile<128, 1024>(wbase, Wq);
    asm volatile("cp.async.commit_group;");
    #pragma unroll
    for (int c = 0; c < 4; c++)
        load_Afeat96(base + c * 12288, m0, c, s0, s1, s2);

    #pragma unroll 1
    for (int nt = 0; nt < 6; nt++) {
        float acc[3][4][4];
        #pragma unroll
        for (int i = 0; i < 3; i++)
            #pragma unroll
            for (int j = 0; j < 4; j++)
                #pragma unroll
                for (int q = 0; q < 4; q++) acc[i][j][q] = 0.f;

        #pragma unroll
        for (int kc = 0; kc < 4; kc++) {
            const int gc = nt * 4 + kc;
            if (gc + 1 < 24) {
                const int nnt = (gc + 1) >> 2, nkc = (gc + 1) & 3;
                load_tile<128, 1024>(wbase + ((gc + 1) & 1) * 16384,
                                     Wq + (size_t)nnt * 131072 + nkc * 128);
                asm volatile("cp.async.commit_group;");
                asm volatile("cp.async.wait_group 1;");
            } else {
                asm volatile("cp.async.wait_group 0;");
            }
            __syncthreads();

            const u32 As = base + kc * 12288;
            const u32 Bs = wbase + (gc & 1) * 16384;
            #pragma unroll
            for (int ks = 0; ks < 4; ks++) {
                u32 a[3][4];
                #pragma unroll
                for (int fm = 0; fm < 3; fm++) {
                    int row = warp_m * 48 + fm * 16 + a_row_base;
                    u32 kb = (u32)(ks * 32 + a_kb_sel);
                    u32 ad = As + row * 128 + (kb ^ ((row & 7) << 4));
                    ldsm4(ad, a[fm][0], a[fm][1], a[fm][2], a[fm][3]);
                }
                u32 b[2][4];
                #pragma unroll
                for (int fn = 0; fn < 2; fn++) {
                    int row = warp_n * 32 + fn * 16 + b_row_base;
                    u32 kb = (u32)(ks * 32 + b_kb_sel);
                    u32 bd = Bs + row * 128 + (kb ^ ((row & 7) << 4));
                    ldsm4(bd, b[fn][0], b[fn][1], b[fn][2], b[fn][3]);
                }
                #pragma unroll
                for (int fm = 0; fm < 3; fm++)
                    #pragma unroll
                    for (int f8 = 0; f8 < 4; f8++)
                        mma16816(acc[fm][f8], a[fm],
                                 b[f8 >> 1][(f8 & 1) * 2], b[f8 >> 1][(f8 & 1) * 2 + 1]);
            }
            __syncthreads();
        }

        // park this n-tile's qkv in smem (+bias, bf16)
        #pragma unroll
        for (int fm = 0; fm < 3; fm++) {
            const int r = warp_m * 48 + fm * 16 + quad;
            #pragma unroll
            for (int f8 = 0; f8 < 4; f8++) {
                const int ncol = nt * 128 + warp_n * 32 + f8 * 8 + 2 * tq;
                float2 bv = *(const float2*)&ipb[ncol];
                u32 lo = bf2bits(__floats2bfloat162_rn(acc[fm][f8][0] + bv.x,
                                                       acc[fm][f8][1] + bv.y));
                u32 hi = bf2bits(__floats2bfloat162_rn(acc[fm][f8][2] + bv.x,
                                                       acc[fm][f8][3] + bv.y));
                *(u32*)(qkv_s + (size_t)r * 1536 + ncol * 2)       = lo;
                *(u32*)(qkv_s + (size_t)(r + 8) * 1536 + ncol * 2) = hi;
            }
        }
    }
    __syncthreads();

    // W prologue for out-proj: overlaps attention phase
    load_tile<128, 1024>(wbase, Wo);
    asm volatile("cp.async.commit_group;");

    // ---------------- phase 2: attention; ctx -> A region ----------------
    const int d0 = lane * 8;
    const int ctx_ch = lane >> 3;
    const int ctx_inb = (d0 & 63) * 2;
    #pragma unroll 1
    for (int bl = 0; bl < 4; bl++) {
        int tb = wid * 4 + bl;

        float q[3][8], k[3][8], v[3][8];
        #pragma unroll
        for (int t = 0; t < 3; t++) {
            const char* rp = qkv_s + (size_t)(tb * 3 + t) * 1536 + d0 * 2;
            uint4 qr = *(const uint4*)rp;
            uint4 kr = *(const uint4*)(rp + 512);
            uint4 vr = *(const uint4*)(rp + 1024);
            const u32* qw = (const u32*)&qr;
            const u32* kw = (const u32*)&kr;
            const u32* vw = (const u32*)&vr;
            #pragma unroll
            for (int j = 0; j < 4; j++) {
                float2 qf = __bfloat1622float2(*(const __nv_bfloat162*)&qw[j]);
                float2 kf = __bfloat1622float2(*(const __nv_bfloat162*)&kw[j]);
                float2 vf = __bfloat1622float2(*(const __nv_bfloat162*)&vw[j]);
                q[t][2*j] = qf.x; q[t][2*j+1] = qf.y;
                k[t][2*j] = kf.x; k[t][2*j+1] = kf.y;
                v[t][2*j] = vf.x; v[t][2*j+1] = vf.y;
            }
        }
        float s[3][3];
        #pragma unroll
        for (int t = 0; t < 3; t++)
            #pragma unroll
            for (int u = 0; u < 3; u++) {
                float p = 0.f;
                #pragma unroll
                for (int j = 0; j < 8; j++) p += q[t][j] * k[u][j];
                p += __shfl_xor_sync(0xffffffffu, p, 1);
                p += __shfl_xor_sync(0xffffffffu, p, 2);
                p += __shfl_xor_sync(0xffffffffu, p, 4);
                s[t][u] = p * 0.125f;
            }
        #pragma unroll
        for (int t = 0; t < 3; t++) {
            float mx = fmaxf(s[t][0], fmaxf(s[t][1], s[t][2]));
            float e0 = expf(s[t][0] - mx);
            float e1 = expf(s[t][1] - mx);
            float e2 = expf(s[t][2] - mx);
            float inv = 1.f / (e0 + e1 + e2);
            u32 cw[4];
            #pragma unroll
            for (int j = 0; j < 8; j += 2) {
                float c0 = (e0 * v[0][j]   + e1 * v[1][j]   + e2 * v[2][j])   * inv;
                float c1 = (e0 * v[0][j+1] + e1 * v[1][j+1] + e2 * v[2][j+1]) * inv;
                cw[j >> 1] = bf2bits(__floats2bfloat162_rn(c0, c1));
            }
            int row = tb * 3 + t;
            u32 off = (u32)(row * 128 + ctx_inb);
            off ^= (off >> 3) & 0x70;
            asm volatile("st.shared.v4.b32 [%0], {%1,%2,%3,%4};"
                         :: "r"(base + ctx_ch * 12288 + off),
                            "r"(cw[0]), "r"(cw[1]), "r"(cw[2]), "r"(cw[3]));
        }
    }
    __syncthreads();

    // ---------------- phase 3: out-proj (ctx x out_w hi) -> g_att bf16 -----
    #pragma unroll 1
    for (int nt2 = 0; nt2 < 2; nt2++) {
        float acc[3][4][4];
        #pragma unroll
        for (int i = 0; i < 3; i++)
            #pragma unroll
            for (int j = 0; j < 4; j++)
                #pragma unroll
                for (int q = 0; q < 4; q++) acc[i][j][q] = 0.f;

        #pragma unroll
        for (int kc = 0; kc < 4; kc++) {
            const int gc = nt2 * 4 + kc;
            if (gc + 1 < 8) {
                load_tile<128, 1024>(wbase + ((gc + 1) & 1) * 16384,
                                     Wo + (size_t)((gc + 1) >> 2) * 131072 + ((gc + 1) & 3) * 128);
                asm volatile("cp.async.commit_group;");
                asm volatile("cp.async.wait_group 1;");
            } else {
                asm volatile("cp.async.wait_group 0;");
            }
            __syncthreads();

            const u32 As = base + kc * 12288;
            const u32 Bs = wbase + (gc & 1) * 16384;
            #pragma unroll
            for (int ks = 0; ks < 4; ks++) {
                u32 a[3][4];
                #pragma unroll
                for (int fm = 0; fm < 3; fm++) {
                    int row = warp_m * 48 + fm * 16 + a_row_base;
                    u32 kb = (u32)(ks * 32 + a_kb_sel);
                    u32 ad = As + row * 128 + (kb ^ ((row & 7) << 4));
                    ldsm4(ad, a[fm][0], a[fm][1], a[fm][2], a[fm][3]);
                }
                u32 b[2][4];
                #pragma unroll
                for (int fn = 0; fn < 2; fn++) {
                    int row = warp_n * 32 + fn * 16 + b_row_base;
                    u32 kb = (u32)(ks * 32 + b_kb_sel);
                    u32 bd = Bs + row * 128 + (kb ^ ((row & 7) << 4));
                    ldsm4(bd, b[fn][0], b[fn][1], b[fn][2], b[fn][3]);
                }
                #pragma unroll
                for (int fm = 0; fm < 3; fm++)
                    #pragma unroll
                    for (int f8 = 0; f8 < 4; f8++)
                        mma16816(acc[fm][f8], a[fm],
                                 b[f8 >> 1][(f8 & 1) * 2], b[f8 >> 1][(f8 & 1) * 2 + 1]);
            }
            __syncthreads();
        }

        #pragma unroll
        for (int fm = 0; fm < 3; fm++) {
            const int r = warp_m * 48 + fm * 16 + quad;
            #pragma unroll
            for (int f8 = 0; f8 < 4; f8++) {
                const int ncol = nt2 * 128 + warp_n * 32 + f8 * 8 + 2 * tq;
                float2 bv = *(const float2*)&ob[ncol];
                u32 lo = bf2bits(__floats2bfloat162_rn(acc[fm][f8][0] + bv.x,
                                                       acc[fm][f8][1] + bv.y));
                u32 hi = bf2bits(__floats2bfloat162_rn(acc[fm][f8][2] + bv.x,
                                                       acc[fm][f8][3] + bv.y));
                *(u32*)&g_att[(size_t)(m0 + r) * 256 + ncol]     = lo;
                *(u32*)&g_att[(size_t)(m0 + r + 8) * 256 + ncol] = hi;
            }
        }
    }
}

// ---------------------------------------------------------------------------
// fuse: x = att(bf16) + feat; LN1, gate softmax, fused (fp32), LN2 -> g_hh.
// ---------------------------------------------------------------------------
__global__ __launch_bounds__(256)
void fuse_k(const float* __restrict__ s0, const float* __restrict__ s1,
            const float* __restrict__ s2,
            const float* __restrict__ ln1g, const float* __restrict__ ln1b,
            const float* __restrict__ gw,   const float* __restrict__ gb,
            const float* __restrict__ ln2g, const float* __restrict__ ln2b,
            float* __restrict__ out_fused, int B)
{
    __shared__ float s_gw[2304];
    __shared__ float s_ln[1024];
    for (int i = threadIdx.x; i < 2304; i += 256) s_gw[i] = gw[i];
    if (threadIdx.x < 256) {
        int i = threadIdx.x;
        s_ln[i]       = ln1g[i];
        s_ln[256 + i] = ln1b[i];
        s_ln[512 + i] = ln2g[i];
        s_ln[768 + i] = ln2b[i];
    }
    __syncthreads();

    int warp = threadIdx.x >> 5, lane = threadIdx.x & 31;
    int d0 = lane * 8;
    const float* srcs[3] = {s0, s1, s2};

    for (int b = blockIdx.x * 8 + warp; b < B; b += gridDim.x * 8) {
        float y[3][8];
        float gpart[3] = {0.f, 0.f, 0.f};
        #pragma unroll
        for (int t = 0; t < 3; t++) {
            float iv[8];
            const float* in = srcs[t] + (size_t)b * 256;
            *(float4*)&iv[0] = *(const float4*)(in + d0);
            *(float4*)&iv[4] = *(const float4*)(in + d0 + 4);
            float x[8];
            uint4 ar = *(const uint4*)(g_att + ((size_t)b * 3 + t) * 256 + d0);
            const u32* aw = (const u32*)&ar;
            #pragma unroll
            for (int j = 0; j < 4; j++) {
                float2 af = __bfloat1622float2(*(const __nv_bfloat162*)&aw[j]);
                x[2*j]   = af.x + iv[2*j];
                x[2*j+1] = af.y + iv[2*j+1];
            }
            float s = 0.f;
            #pragma unroll
            for (int j = 0; j < 8; j++) s += x[j];
            s = wsum(s);
            float mu = s * (1.f / 256.f);
            float vv = 0.f;
            #pragma unroll
            for (int j = 0; j < 8; j++) { float d = x[j] - mu; vv += d * d; }
            vv = wsum(vv);
            float rs = rsqrtf(vv * (1.f / 256.f) + 1e-5f);
            #pragma unroll
            for (int j = 0; j < 8; j++)
                y[t][j] = (x[j] - mu) * rs * s_ln[d0 + j] + s_ln[256 + d0 + j];

            #pragma unroll
            for (int g = 0; g < 3; g++) {
                const float* wrow = s_gw + g * 768 + t * 256 + d0;
                #pragma unroll
                for (int j = 0; j < 8; j++) gpart[g] += iv[j] * wrow[j];
            }
        }
        float gl[3];
        #pragma unroll
        for (int g = 0; g < 3; g++) gl[g] = wsum(gpart[g]) + gb[g];
        float mx = fmaxf(gl[0], fmaxf(gl[1], gl[2]));
        float e0 = expf(gl[0] - mx), e1 = expf(gl[1] - mx), e2 = expf(gl[2] - mx);
        float inv = 1.f / (e0 + e1 + e2);
        float w0 = e0 * inv, w1 = e1 * inv, w2 = e2 * inv;

        float f[8];
        #pragma unroll
        for (int j = 0; j < 8; j++)
            f[j] = w0 * y[0][j] + w1 * y[1][j] + w2 * y[2][j];
        if (out_fused) {
            float* orow = out_fused + (size_t)b * 256 + d0;
            *(float4*)orow       = *(float4*)&f[0];
            *(float4*)(orow + 4) = *(float4*)&f[4];
        }
        float s2v = 0.f;
        #pragma unroll
        for (int j = 0; j < 8; j++) s2v += f[j];
        s2v = wsum(s2v);
        float mu2 = s2v * (1.f / 256.f);
        float vv2 = 0.f;
        #pragma unroll
        for (int j = 0; j < 8; j++) { float d = f[j] - mu2; vv2 += d * d; }
        vv2 = wsum(vv2);
        float rs2 = rsqrtf(vv2 * (1.f / 256.f) + 1e-5f);
        u32 hi[4], lo[4];
        #pragma unroll
        for (int j = 0; j < 8; j += 2) {
            float h0 = (f[j]   - mu2) * rs2 * s_ln[512 + d0 + j]   + s_ln[768 + d0 + j];
            float h1 = (f[j+1] - mu2) * rs2 * s_ln[512 + d0 + j+1] + s_ln[768 + d0 + j+1];
            split2(h0, h1, hi[j >> 1], lo[j >> 1]);
        }
        __nv_bfloat16* hrow = g_hh + (size_t)b * 512 + d0;
        *(uint4*)hrow         = *(uint4*)hi;
        *(uint4*)(hrow + 256) = *(uint4*)lo;
    }
}

// ---------------------------------------------------------------------------
// deephead (occ-2): M_TILE=64, A streamed (2x8K), W streamed (2x16K),
// H2 resident (8x8K = 64K). Total 112K -> 2 CTAs/SM.
// hh -> (w1 split, GELU) -> h2(smem split) -> (w2 split, GELU) -> h3 -> logits
// ---------------------------------------------------------------------------
__global__ __launch_bounds__(256, 2)
void deephead(const float* __restrict__ b1, const float* __restrict__ b2,
              const float* __restrict__ w3p, const float* __restrict__ b3p,
              float* __restrict__ outp)
{
    extern __shared__ char dsm[];
    char* dbase = (char*)((((uintptr_t)dsm) + 127) & ~(uintptr_t)127);
    u32 base = smem_u32(dbase);
    const u32 abase = base;              // 2 x 8192
    const u32 wbase = base + 16384;      // 2 x 16384
    const u32 hbase = base + 49152;      // 8 x 8192

    const int tid = threadIdx.x;
    const int lane = tid & 31;
    const int wid = tid >> 5;
    const int warp_m = wid & 1;          // 32 rows each
    const int warp_n = wid >> 1;         // 32 cols each
    const int m0 = blockIdx.x * 64;

    const char* Ab  = (const char*)g_hh + (size_t)m0 * 1024;
    const char* W1b = (const char*)(g_w + WOFF_W1);
    const char* W2b = (const char*)(g_w + WOFF_W2);

    const int a_idx12[12] = {0,1,2,3, 0,1,2,3, 4,5,6,7};
    const int w_idx12[12] = {0,1,2,3, 4,5,6,7, 0,1,2,3};

    const int a_mi = lane >> 3;
    const int a_row_base = ((a_mi & 1) << 3) + (lane & 7);
    const int a_kb_sel = (lane >> 4) << 4;
    const int b_row_base = ((a_mi >> 1) << 3) + (lane & 7);
    const int b_kb_sel = ((lane >> 3) & 1) << 4;
    const int quad = lane >> 2, tq = lane & 3;

    float acc[2][4][4];
    #pragma unroll
    for (int i = 0; i < 2; i++)
        #pragma unroll
        for (int j = 0; j < 4; j++)
            #pragma unroll
            for (int q = 0; q < 4; q++) acc[i][j][q] = 0.f;

    // prologue: chunk g=0 (A chunk a_idx12[0]=0, W1 nt0 chunk 0)
    load_tile<64, 1024>(abase, Ab);
    load_tile<128, 1024>(wbase, W1b);
    asm volatile("cp.async.commit_group;");

    // ---------------- phase 1: h2 = GELU(hh @ w1^T + b1) --------------------
    #pragma unroll 1
    for (int g = 0; g < 24; g++) {
        const int nt = g / 12, kc = g - nt * 12;
        if (g < 23) {
            const int g1 = g + 1;
            const int nt1 = g1 / 12, kc1 = g1 - nt1 * 12;
            load_tile<64, 1024>(abase + (g1 & 1) * 8192, Ab + a_idx12[kc1] * 128);
            load_tile<128, 1024>(wbase + (g1 & 1) * 16384,
                                 W1b + (size_t)nt1 * 131072 + w_idx12[kc1] * 128);
        } else {
            // prefetch W2 chunk 0 into buffer (24 & 1) = 0
            load_tile<128, 1024>(wbase, W2b + w_idx12[0] * 128);
        }
        asm volatile("cp.async.commit_group;");
        asm volatile("cp.async.wait_group 1;");
        __syncthreads();

        const u32 As = abase + (g & 1) * 8192;
        const u32 Bs = wbase + (g & 1) * 16384;
        #pragma unroll
        for (int ks = 0; ks < 4; ks++) {
            u32 a[2][4];
            #pragma unroll
            for (int fm = 0; fm < 2; fm++) {
                int row = warp_m * 32 + fm * 16 + a_row_base;
                u32 kb = (u32)(ks * 32 + a_kb_sel);
                u32 ad = As + row * 128 + (kb ^ ((row & 7) << 4));
                ldsm4(ad, a[fm][0], a[fm][1], a[fm][2], a[fm][3]);
            }
            u32 b[2][4];
            #pragma unroll
            for (int fn = 0; fn < 2; fn++) {
                int row = warp_n * 32 + fn * 16 + b_row_base;
                u32 kb = (u32)(ks * 32 + b_kb_sel);
                u32 bd = Bs + row * 128 + (kb ^ ((row & 7) << 4));
                ldsm4(bd, b[fn][0], b[fn][1], b[fn][2], b[fn][3]);
            }
            #pragma unroll
            for (int fm = 0; fm < 2; fm++)
                #pragma unroll
                for (int f8 = 0; f8 < 4; f8++)
                    mma16816(acc[fm][f8], a[fm],
                             b[f8 >> 1][(f8 & 1) * 2], b[f8 >> 1][(f8 & 1) * 2 + 1]);
        }
        __syncthreads();

        if (kc == 11) {
            // epilogue: GELU + split -> H2 chunks (hi: 0-3, lo: 4-7)
            #pragma unroll
            for (int fm = 0; fm < 2; fm++) {
                #pragma unroll
                for (int f8 = 0; f8 < 4; f8++) {
                    const int ncol = nt * 128 + warp_n * 32 + f8 * 8 + 2 * tq;
                    float2 bv = *(const float2*)&b1[ncol];
                    float v0 = geluf(acc[fm][f8][0] + bv.x);
                    float v1 = geluf(acc[fm][f8][1] + bv.y);
                    float v2 = geluf(acc[fm][f8][2] + bv.x);
                    float v3 = geluf(acc[fm][f8][3] + bv.y);
                    u32 h0, l0, h1, l1;
                    split2(v0, v1, h0, l0);
                    split2(v2, v3, h1, l1);
                    const int chl = ncol >> 6;                  // 0..3
                    const u32 hi_slot = hbase + chl * 8192;
                    const u32 lo_slot = hbase + 32768 + chl * 8192;
                    const int bb = (ncol & 63) * 2;
                    const int r0 = warp_m * 32 + fm * 16 + quad;
                    #pragma unroll
                    for (int wh = 0; wh < 2; wh++) {
                        int row = r0 + wh * 8;
                        u32 off = (u32)(row * 128 + (bb & ~15));
                        off ^= (off >> 3) & 0x70;
                        off += (u32)(bb & 15);
                        u32 hv = wh ? h1 : h0;
                        u32 lv = wh ? l1 : l0;
                        asm volatile("st.shared.b32 [%0], %1;" :: "r"(hi_slot + off), "r"(hv));
                        asm volatile("st.shared.b32 [%0], %1;" :: "r"(lo_slot + off), "r"(lv));
                    }
                    acc[fm][f8][0] = 0.f; acc[fm][f8][1] = 0.f;
                    acc[fm][f8][2] = 0.f; acc[fm][f8][3] = 0.f;
                }
            }
        }
    }

    // ---------------- phase 2: h3 = GELU(h2 @ w2^T + b2) --------------------
    #pragma unroll 1
    for (int j = 0; j < 12; j++) {
        if (j < 11) {
            load_tile<128, 1024>(wbase + ((25 + j) & 1) * 16384,
                                 W2b + w_idx12[j + 1] * 128);
            asm volatile("cp.async.commit_group;");
            asm volatile("cp.async.wait_group 1;");
        } else {
            asm volatile("cp.async.wait_group 0;");
        }
        __syncthreads();

        const u32 As = hbase + a_idx12[j] * 8192;
        const u32 Bs = wbase + ((24 + j) & 1) * 16384;
        #pragma unroll
        for (int ks = 0; ks < 4; ks++) {
            u32 a[2][4];
            #pragma unroll
            for (int fm = 0; fm < 2; fm++) {
                int row = warp_m * 32 + fm * 16 + a_row_base;
                u32 kb = (u32)(ks * 32 + a_kb_sel);
                u32 ad = As + row * 128 + (kb ^ ((row & 7) << 4));
                ldsm4(ad, a[fm][0], a[fm][1], a[fm][2], a[fm][3]);
            }
            u32 b[2][4];
            #pragma unroll
            for (int fn = 0; fn < 2; fn++) {
                int row = warp_n * 32 + fn * 16 + b_row_base;
                u32 kb = (u32)(ks * 32 + b_kb_sel);
                u32 bd = Bs + row * 128 + (kb ^ ((row & 7) << 4));
                ldsm4(bd, b[fn][0], b[fn][1], b[fn][2], b[fn][3]);
            }
            #pragma unroll
            for (int fm = 0; fm < 2; fm++)
                #pragma unroll
                for (int f8 = 0; f8 < 4; f8++)
                    mma16816(acc[fm][f8], a[fm],
                             b[f8 >> 1][(f8 & 1) * 2], b[f8 >> 1][(f8 & 1) * 2 + 1]);
        }
        __syncthreads();
    }

    // h3 -> smem fp32 [64][128] at H2 region (dead now)
    float* h3_s = (float*)(dbase + 49152);
    #pragma unroll
    for (int fm = 0; fm < 2; fm++) {
        #pragma unroll
        for (int f8 = 0; f8 < 4; f8++) {
            const int n = warp_n * 32 + f8 * 8 + 2 * tq;
            float2 bv = *(const float2*)&b2[n];
            int rl = warp_m * 32 + fm * 16 + quad;
            *(float2*)&h3_s[rl * 128 + n] =
                {geluf(acc[fm][f8][0] + bv.x), geluf(acc[fm][f8][1] + bv.y)};
            *(float2*)&h3_s[(rl + 8) * 128 + n] =
                {geluf(acc[fm][f8][2] + bv.x), geluf(acc[fm][f8][3] + bv.y)};
        }
    }
    __syncthreads();

    // logits: 64 rows, 8 warps -> 8 rows each; w3/b3 straight from L2
    const int d0 = lane * 4;
    float4 wv[7];
    #pragma unroll
    for (int j = 0; j < 7; j++) wv[j] = *(const float4*)&w3p[j * 128 + d0];
    #pragma unroll 1
    for (int rr = 0; rr < 8; rr++) {
        int row = wid * 8 + rr;
        float4 h = *(const float4*)&h3_s[row * 128 + d0];
        float r[7];
        #pragma unroll
        for (int j = 0; j < 7; j++) {
            float p = h.x * wv[j].x + h.y * wv[j].y + h.z * wv[j].z + h.w * wv[j].w;
            r[j] = wsum(p);
        }
        if (lane == 0) {
            #pragma unroll
            for (int j = 0; j < 7; j++)
                outp[(size_t)(m0 + row) * 7 + j] = r[j] + b3p[j];
        }
    }
}

// ---------------------------------------------------------------------------
extern "C" void kernel_launch(void* const* d_in, const int* in_sizes, int n_in,
                              void* d_out, int out_size)
{
    const float* f_swin    = (const float*)d_in[0];
    const float* f_maxvit  = (const float*)d_in[1];
    const float* f_focal   = (const float*)d_in[2];
    const float* in_proj_w = (const float*)d_in[3];
    const float* in_proj_b = (const float*)d_in[4];
    const float* out_w  = (const float*)d_in[5];
    const float* out_b  = (const float*)d_in[6];
    const float* ln1_g  = (const float*)d_in[7];
    const float* ln1_b  = (const float*)d_in[8];
    const float* gate_w = (const float*)d_in[9];
    const float* gate_b = (const float*)d_in[10];
    const float* ln2_g  = (const float*)d_in[11];
    const float* ln2_b  = (const float*)d_in[12];
    const float* w1 = (const float*)d_in[13];
    const float* b1 = (const float*)d_in[14];
    const float* w2 = (const float*)d_in[15];
    const float* b2 = (const float*)d_in[16];
    const float* w3 = (const float*)d_in[17];
    const float* b3 = (const float*)d_in[18];

    int B = in_sizes[0] / 256;
    if (B > BMAX) B = BMAX;
    int rows3 = 3 * B;

    float* outp = (float*)d_out;
    float* out_logits = outp;
    float* out_fused = (out_size >= B * 263) ? (outp + (size_t)B * 7) : nullptr;

    const int SMEM_QA = 49152 + 32768 + 147456 + 1024;   // 230400
    const int SMEM_DH = 16384 + 32768 + 65536 + 128;     // 114816 (occ 2)
    cudaFuncSetAttribute(qkv_attn_out, cudaFuncAttributeMaxDynamicSharedMemorySize, SMEM_QA);
    cudaFuncSetAttribute(deephead, cudaFuncAttributeMaxDynamicSharedMemorySize, SMEM_DH);

    dim3 blk(256);

    conv_w_all<<<352, blk>>>(in_proj_w, out_w, w1, w2);
    // fused qkv + attention + out-proj
    qkv_attn_out<<<rows3 / 96, blk, SMEM_QA>>>(in_proj_b, out_b,
                                               f_swin, f_maxvit, f_focal);
    // residual + LN1 + gate + fused + LN2
    fuse_k<<<2048, blk>>>(f_swin, f_maxvit, f_focal,
                          ln1_g, ln1_b, gate_w, gate_b, ln2_g, ln2_b,
                          out_fused, B);
    // deep head fused (occ 2)
    deephead<<<B / 64, blk, SMEM_DH>>>(b1, b2, w3, b3, out_logits);
}